// round 14
// baseline (speedup 1.0000x reference)
#include <cuda_runtime.h>
#include <cuda_bf16.h>
#include <cuda_fp16.h>
#include <cstdint>

#define BB 4
#define SS 2048
#define EE 1024
#define HH 16
#define DD 64
#define M_TOT (BB * SS)     // 8192
#define KDIM EE             // GEMM K = 1024

// operands (all fp16)
__device__ __half g_xh[M_TOT * EE],   g_xs2[M_TOT * EE];          // x 2-term fp16 [M][K]
__device__ __half g_wah[3 * EE * EE];                             // w_attn single fp16 [N][K]
__device__ __half g_wph[EE * EE];                                 // w_proj single fp16 [N][K]
__device__ __half g_qh[BB * HH * SS * DD], g_qs2[BB * HH * SS * DD]; // q 2-term fp16 [b,h,s,d]
__device__ __half g_kh[BB * HH * SS * DD], g_ks2[BB * HH * SS * DD]; // k 2-term fp16 [b,h,s,d]
__device__ __half g_vh[BB * HH * DD * SS];                        // v single fp16 [b,h,d,s]
__device__ __half g_yh[M_TOT * EE];                               // y single fp16 [M][E]

// ---------------------------------------------------------------------------
// Helpers
// ---------------------------------------------------------------------------
__device__ __forceinline__ uint32_t sm2u32(const void* p) {
    uint32_t a;
    asm("{ .reg .u64 t; cvta.to.shared.u64 t, %1; cvt.u32.u64 %0, t; }"
        : "=r"(a) : "l"(p));
    return a;
}

__device__ __forceinline__ uint32_t packh(float lo, float hi) {
    uint32_t r;
    asm("cvt.rn.f16x2.f32 %0, %1, %2;" : "=r"(r) : "f"(hi), "f"(lo));
    return r;
}

__device__ __forceinline__ void mma_f16(float* c, const uint32_t* a,
                                        uint32_t b0, uint32_t b1) {
    asm volatile(
        "mma.sync.aligned.m16n8k16.row.col.f32.f16.f16.f32 "
        "{%0,%1,%2,%3}, {%4,%5,%6,%7}, {%8,%9}, {%0,%1,%2,%3};\n"
        : "+f"(c[0]), "+f"(c[1]), "+f"(c[2]), "+f"(c[3])
        : "r"(a[0]), "r"(a[1]), "r"(a[2]), "r"(a[3]), "r"(b0), "r"(b1));
}

__device__ __forceinline__ void ldm4(uint32_t addr, uint32_t* r) {
    asm volatile("ldmatrix.sync.aligned.m8n8.x4.shared.b16 {%0,%1,%2,%3}, [%4];"
                 : "=r"(r[0]), "=r"(r[1]), "=r"(r[2]), "=r"(r[3]) : "r"(addr));
}

#define CP16(dst, src) \
    asm volatile("cp.async.cg.shared.global [%0], [%1], 16;" :: "r"(dst), "l"(src))
#define CP_COMMIT() asm volatile("cp.async.commit_group;")

// ---------------------------------------------------------------------------
// Prep kernels
// ---------------------------------------------------------------------------
__global__ void split_h_kernel(const float* __restrict__ in,
                               __half* __restrict__ ob,
                               __half* __restrict__ os, int n4)
{
    int i = blockIdx.x * blockDim.x + threadIdx.x;
    if (i >= n4) return;
    float4 v = ((const float4*)in)[i];
    float f[4] = {v.x, v.y, v.z, v.w};
    uint2 pb, ps;
    __half* bb = (__half*)&pb;
    __half* ss = (__half*)&ps;
#pragma unroll
    for (int e = 0; e < 4; e++) {
        __half b = __float2half_rn(f[e]);
        bb[e] = b;
        ss[e] = __float2half_rn(f[e] - __half2float(b));
    }
    ((uint2*)ob)[i] = pb;
    ((uint2*)os)[i] = ps;
}

// w[K,N] fp32 -> oh [N,K] single fp16
__global__ void transpose_h_kernel(const float* __restrict__ w,
                                   __half* __restrict__ oh, int K, int N)
{
    __shared__ float t[32][33];
    int n0 = blockIdx.x * 32, k0 = blockIdx.y * 32;
    int tx = threadIdx.x, ty = threadIdx.y;
#pragma unroll
    for (int i = 0; i < 4; i++)
        t[ty + i * 8][tx] = w[(size_t)(k0 + ty + i * 8) * N + n0 + tx];
    __syncthreads();
#pragma unroll
    for (int i = 0; i < 4; i++) {
        int n = ty + i * 8;
        oh[(size_t)(n0 + n) * K + k0 + tx] = __float2half_rn(t[tx][n]);
    }
}

// ---------------------------------------------------------------------------
// QKV GEMM: uniform 2-mma fp16: acc += (xb + xs) * wb. Block 128x128, warp
// tile 64x32, occ 2, KT=32, 3-stage cp.async pipeline (24KB stages).
// Stage arrays: Ab | As | Bb (w-small eliminated).
// Epilogue: q/k -> fp16 2-term [b,h,s,d]; v -> single fp16 [b,h,d,s].
// ---------------------------------------------------------------------------
#define GKT 32
#define NKT (KDIM / GKT)           // 32
#define GARR_B 8192                // 128 rows * 64 B
#define GSTAGE_B (3 * GARR_B)      // 24576
#define GEMM_DSMEM (3 * GSTAGE_B)  // 73728

__global__ __launch_bounds__(256, 2) void h_gemm_qkv(
    const __half* __restrict__ Ab, const __half* __restrict__ As_,
    const __half* __restrict__ Btb)
{
    extern __shared__ uint32_t sw4[];
    const uint32_t sbase = sm2u32(sw4);

    const int tid  = threadIdx.x;
    const int lane = tid & 31;
    const int g    = lane >> 2;
    const int t4   = lane & 3;
    const int m_   = lane >> 3;
    const int j_   = lane & 7;
    const int warp = tid >> 5;
    const int wm   = warp & 1;
    const int wn   = warp >> 1;
    const int m0   = blockIdx.y * 128;
    const int n0   = blockIdx.x * 128;

    const char* srcs[3] = {
        (const char*)(Ab  + (size_t)m0 * KDIM),
        (const char*)(As_ + (size_t)m0 * KDIM),
        (const char*)(Btb + (size_t)n0 * KDIM) };

    int arow[4], asw[4];
#pragma unroll
    for (int mt = 0; mt < 4; mt++) {
        arow[mt] = wm * 64 + mt * 16 + ((m_ & 1) << 3) + j_;
        asw[mt]  = (arow[mt] >> 1) & 3;
    }
    int brow[2], bsw[2];
#pragma unroll
    for (int p = 0; p < 2; p++) {
        brow[p] = wn * 32 + p * 16 + ((m_ >> 1) << 3) + j_;
        bsw[p]  = (brow[p] >> 1) & 3;
    }

    float acc[4][4][4];
#pragma unroll
    for (int i = 0; i < 4; i++)
#pragma unroll
        for (int j = 0; j < 4; j++)
#pragma unroll
            for (int e = 0; e < 4; e++) acc[i][j][e] = 0.0f;

    auto load_stage = [&](int s, int kt) {
        const uint32_t stb = sbase + s * GSTAGE_B;
#pragma unroll
        for (int i = 0; i < 6; i++) {
            const int arr = i >> 1;
            int local = ((i & 1) << 8) + tid;       // 0..511
            int row = local >> 2;
            int c   = local & 3;
            uint32_t dst = stb + arr * GARR_B + row * 64 +
                           ((c ^ ((row >> 1) & 3)) << 4);
            const char* src = srcs[arr] + (size_t)row * (KDIM * 2) + kt * 64 + c * 16;
            CP16(dst, src);
        }
        CP_COMMIT();
    };

    load_stage(0, 0);
    load_stage(1, 1);

    for (int kt = 0; kt < NKT; kt++) {
        const int s = kt % 3;
        if (kt + 1 < NKT) {
            asm volatile("cp.async.wait_group 1;");
        } else {
            asm volatile("cp.async.wait_group 0;");
        }
        __syncthreads();
        if (kt + 2 < NKT) load_stage((kt + 2) % 3, kt + 2);

        const uint32_t AbO = sbase + s * GSTAGE_B;
        const uint32_t AsO = AbO + GARR_B;
        const uint32_t BbO = AbO + 2 * GARR_B;

#pragma unroll
        for (int ks = 0; ks < 2; ks++) {
            const int cA = ks * 2 + (m_ >> 1);
            const int cB = ks * 2 + (m_ & 1);

            uint32_t bb[4][2];
#pragma unroll
            for (int p = 0; p < 2; p++) {
                uint32_t off = brow[p] * 64 + ((cB ^ bsw[p]) << 4);
                uint32_t r[4];
                ldm4(BbO + off, r);
                bb[2 * p][0] = r[0];     bb[2 * p][1] = r[1];
                bb[2 * p + 1][0] = r[2]; bb[2 * p + 1][1] = r[3];
            }
#pragma unroll
            for (int mt = 0; mt < 4; mt++) {
                uint32_t off = arow[mt] * 64 + ((cA ^ asw[mt]) << 4);
                uint32_t ab[4], asf[4];
                ldm4(AbO + off, ab);
                ldm4(AsO + off, asf);
#pragma unroll
                for (int nt = 0; nt < 4; nt++)
                    mma_f16(acc[mt][nt], ab,  bb[nt][0], bb[nt][1]);
#pragma unroll
                for (int nt = 0; nt < 4; nt++)
                    mma_f16(acc[mt][nt], asf, bb[nt][0], bb[nt][1]);
            }
        }
    }

    // ---- epilogue: q/k fp16 2-term, v single fp16 transposed ----
#pragma unroll
    for (int mt = 0; mt < 4; mt++) {
#pragma unroll
        for (int nt = 0; nt < 4; nt++) {
            const int r  = m0 + wm * 64 + mt * 16 + g;
            const int cc = n0 + wn * 32 + nt * 8 + 2 * t4;
            float v0 = acc[mt][nt][0], v1 = acc[mt][nt][1];
            float v2 = acc[mt][nt][2], v3 = acc[mt][nt][3];
            const int sec = cc >> 10;
            const int c10 = cc & 1023;
            const int h   = c10 >> 6;
            const int d0  = c10 & 63;
            const int b   = r >> 11;
            const int sl  = r & 2047;
            if (sec < 2) {
                float b0 = __half2float(__float2half_rn(v0));
                float b1 = __half2float(__float2half_rn(v1));
                float b2 = __half2float(__float2half_rn(v2));
                float b3 = __half2float(__float2half_rn(v3));
                __half* dh = (sec == 0) ? g_qh  : g_kh;
                __half* ds = (sec == 0) ? g_qs2 : g_ks2;
                size_t i0 = (((size_t)(b * HH + h)) * SS + sl) * DD + d0;
                *(uint32_t*)&dh[i0] = packh(b0, b1);
                *(uint32_t*)&ds[i0] = packh(v0 - b0, v1 - b1);
                *(uint32_t*)&dh[i0 + 8 * DD] = packh(b2, b3);
                *(uint32_t*)&ds[i0 + 8 * DD] = packh(v2 - b2, v3 - b3);
            } else {
                size_t base = ((size_t)(b * HH + h)) * DD * SS;
                size_t iA = base + (size_t)d0 * SS + sl;
                size_t iB = base + (size_t)(d0 + 1) * SS + sl;
                g_vh[iA]     = __float2half_rn(v0);
                g_vh[iB]     = __float2half_rn(v1);
                g_vh[iA + 8] = __float2half_rn(v2);
                g_vh[iB + 8] = __float2half_rn(v3);
            }
        }
    }
}

// ---------------------------------------------------------------------------
// Proj GEMM: single fp16, 1 mma per acc per k-chunk (unchanged).
// ---------------------------------------------------------------------------
#define HARR_B 8192
#define HSTAGE_B (2 * HARR_B)      // 16384
#define HG_DSMEM (3 * HSTAGE_B)    // 49152

__global__ __launch_bounds__(256, 2) void h_gemm(
    const __half* __restrict__ Ah, const __half* __restrict__ Bh,
    float* __restrict__ C, int Ncols)
{
    extern __shared__ uint32_t sw4[];
    const uint32_t sbase = sm2u32(sw4);

    const int tid  = threadIdx.x;
    const int lane = tid & 31;
    const int g    = lane >> 2;
    const int t4   = lane & 3;
    const int m_   = lane >> 3;
    const int j_   = lane & 7;
    const int warp = tid >> 5;
    const int wm   = warp & 1;
    const int wn   = warp >> 1;
    const int m0   = blockIdx.y * 128;
    const int n0   = blockIdx.x * 128;

    const char* srcs[2] = {
        (const char*)(Ah + (size_t)m0 * KDIM),
        (const char*)(Bh + (size_t)n0 * KDIM) };

    int arow[4], asw[4];
#pragma unroll
    for (int mt = 0; mt < 4; mt++) {
        arow[mt] = wm * 64 + mt * 16 + ((m_ & 1) << 3) + j_;
        asw[mt]  = (arow[mt] >> 1) & 3;
    }
    int brow[2], bsw[2];
#pragma unroll
    for (int p = 0; p < 2; p++) {
        brow[p] = wn * 32 + p * 16 + ((m_ >> 1) << 3) + j_;
        bsw[p]  = (brow[p] >> 1) & 3;
    }

    float acc[4][4][4];
#pragma unroll
    for (int i = 0; i < 4; i++)
#pragma unroll
        for (int j = 0; j < 4; j++)
#pragma unroll
            for (int e = 0; e < 4; e++) acc[i][j][e] = 0.0f;

    auto load_stage = [&](int s, int kt) {
        const uint32_t stb = sbase + s * HSTAGE_B;
#pragma unroll
        for (int i = 0; i < 4; i++) {
            const int arr = i >> 1;
            int local = ((i & 1) << 8) + tid;
            int row = local >> 2;
            int c   = local & 3;
            uint32_t dst = stb + arr * HARR_B + row * 64 +
                           ((c ^ ((row >> 1) & 3)) << 4);
            const char* src = srcs[arr] + (size_t)row * (KDIM * 2) + kt * 64 + c * 16;
            CP16(dst, src);
        }
        CP_COMMIT();
    };

    load_stage(0, 0);
    load_stage(1, 1);

    for (int kt = 0; kt < NKT; kt++) {
        const int s = kt % 3;
        if (kt + 1 < NKT) {
            asm volatile("cp.async.wait_group 1;");
        } else {
            asm volatile("cp.async.wait_group 0;");
        }
        __syncthreads();
        if (kt + 2 < NKT) load_stage((kt + 2) % 3, kt + 2);

        const uint32_t AO = sbase + s * HSTAGE_B;
        const uint32_t BO = AO + HARR_B;

#pragma unroll
        for (int ks = 0; ks < 2; ks++) {
            const int cA = ks * 2 + (m_ >> 1);
            const int cB = ks * 2 + (m_ & 1);

            uint32_t bb[4][2];
#pragma unroll
            for (int p = 0; p < 2; p++) {
                uint32_t off = brow[p] * 64 + ((cB ^ bsw[p]) << 4);
                uint32_t r[4];
                ldm4(BO + off, r);
                bb[2 * p][0] = r[0];     bb[2 * p][1] = r[1];
                bb[2 * p + 1][0] = r[2]; bb[2 * p + 1][1] = r[3];
            }
#pragma unroll
            for (int mt = 0; mt < 4; mt++) {
                uint32_t off = arow[mt] * 64 + ((cA ^ asw[mt]) << 4);
                uint32_t ab[4];
                ldm4(AO + off, ab);
#pragma unroll
                for (int nt = 0; nt < 4; nt++)
                    mma_f16(acc[mt][nt], ab, bb[nt][0], bb[nt][1]);
            }
        }
    }

#pragma unroll
    for (int mt = 0; mt < 4; mt++) {
#pragma unroll
        for (int nt = 0; nt < 4; nt++) {
            const int r  = m0 + wm * 64 + mt * 16 + g;
            const int cc = n0 + wn * 32 + nt * 8 + 2 * t4;
            size_t i0 = (size_t)r * Ncols + cc;
            *(float2*)&C[i0] = make_float2(acc[mt][nt][0], acc[mt][nt][1]);
            *(float2*)&C[i0 + (size_t)8 * Ncols] =
                make_float2(acc[mt][nt][2], acc[mt][nt][3]);
        }
    }
}

// ---------------------------------------------------------------------------
// Tensor-core flash attention (unchanged from R13). QK^T: 3-term fp16.
// PV: P single fp16, V single fp16 (2 mmas/chunk). y single fp16.
// ---------------------------------------------------------------------------
#define FQ_B   16384
#define FARR_B 8192
#define FSTAGE_B (3 * FARR_B)                  // Kh,Ks2,Vh = 24576
#define FLASH_SMEM (2 * FQ_B + 2 * FSTAGE_B)   // 81920

__global__ __launch_bounds__(256, 2) void flash_tc(void)
{
    extern __shared__ uint32_t fw4[];
    const uint32_t sbase = sm2u32(fw4);

    const int tid  = threadIdx.x;
    const int lane = tid & 31;
    const int g    = lane >> 2;
    const int t4   = lane & 3;
    const int m_   = lane >> 3;
    const int j_   = lane & 7;
    const int w    = tid >> 5;
    const int qt   = (int)gridDim.x - 1 - (int)blockIdx.x;  // longest-first
    const int bh   = blockIdx.y;
    const int q0   = qt * 128;
    const int b    = bh >> 4, h = bh & 15;

    const char* qb_src = (const char*)(g_qh  + ((size_t)bh * SS + q0) * DD);
    const char* qs_src = (const char*)(g_qs2 + ((size_t)bh * SS + q0) * DD);
    const char* kb_base = (const char*)(g_kh  + (size_t)bh * SS * DD);
    const char* ks_base = (const char*)(g_ks2 + (size_t)bh * SS * DD);
    const char* vh_base = (const char*)(g_vh  + (size_t)bh * DD * SS);

    const int qrow_l = 16 * w + ((m_ & 1) << 3) + j_;
    const int qsw    = qrow_l & 7;
    int krow[4], ksw[4];
#pragma unroll
    for (int p = 0; p < 4; p++) {
        krow[p] = p * 16 + ((m_ >> 1) << 3) + j_;
        ksw[p]  = krow[p] & 7;
    }

    // ---- prologue loads: Q (2 arrays) + KV stage 0 (3 arrays) ----
#pragma unroll
    for (int i = 0; i < 8; i++) {
        const int arr = i >> 2;
        int local = ((i & 3) << 8) + tid;
        int row = local >> 3, c = local & 7;
        uint32_t dst = sbase + arr * FQ_B + row * 128 + ((c ^ (row & 7)) << 4);
        const char* src = (arr ? qs_src : qb_src) + (size_t)row * 128 + c * 16;
        CP16(dst, src);
    }
#pragma unroll
    for (int i = 0; i < 6; i++) {
        const int arr = i >> 1;
        int local = ((i & 1) << 8) + tid;
        int row = local >> 3, c = local & 7;
        uint32_t dst = sbase + 2 * FQ_B + arr * FARR_B + row * 128 +
                       ((c ^ (row & 7)) << 4);
        const char* src;
        if (arr == 0)      src = kb_base + (size_t)row * 128 + c * 16;
        else if (arr == 1) src = ks_base + (size_t)row * 128 + c * 16;
        else               src = vh_base + (size_t)row * (SS * 2) + c * 16;
        CP16(dst, src);
    }
    CP_COMMIT();

    float s4[8][4], y[8][4];
#pragma unroll
    for (int j = 0; j < 8; j++)
#pragma unroll
        for (int e = 0; e < 4; e++) y[j][e] = 0.0f;
    float m0 = -1e30f, m1 = -1e30f, l0 = 0.0f, l1 = 0.0f;

    const int qrow0 = q0 + 16 * w + g;
    const int qlim  = q0 + 16 * w + 15;
    const int jmax  = 2 * qt + 2;

    for (int jt = 0; jt < jmax; jt++) {
        const int s  = jt & 1;
        const int k0 = jt * 64;

        if (jt + 1 < jmax) {
            const int kn = (jt + 1) * 64;
            const uint32_t stb = sbase + 2 * FQ_B + (s ^ 1) * FSTAGE_B;
#pragma unroll
            for (int i = 0; i < 6; i++) {
                const int arr = i >> 1;
                int local = ((i & 1) << 8) + tid;
                int row = local >> 3, c = local & 7;
                uint32_t dst = stb + arr * FARR_B + row * 128 + ((c ^ (row & 7)) << 4);
                const char* src;
                if (arr == 0)      src = kb_base + ((size_t)(kn + row)) * 128 + c * 16;
                else if (arr == 1) src = ks_base + ((size_t)(kn + row)) * 128 + c * 16;
                else               src = vh_base + (size_t)row * (SS * 2) + kn * 2 + c * 16;
                CP16(dst, src);
            }
            CP_COMMIT();
            asm volatile("cp.async.wait_group 1;");
        } else {
            asm volatile("cp.async.wait_group 0;");
        }
        __syncthreads();

        const bool active = (k0 <= qlim);
        if (active) {
            const uint32_t KbO = sbase + 2 * FQ_B + s * FSTAGE_B;
            const uint32_t KsO = KbO + FARR_B;
            const uint32_t VhO = KbO + 2 * FARR_B;

            // ---- S = Q K^T (3-term fp16, causal skip per 16-key pair) ----
#pragma unroll
            for (int j = 0; j < 8; j++)
#pragma unroll
                for (int e = 0; e < 4; e++) s4[j][e] = 0.0f;

#pragma unroll
            for (int ks = 0; ks < 4; ks++) {
                const int cA = ks * 2 + (m_ >> 1);
                const int cB = ks * 2 + (m_ & 1);
                uint32_t qoff = qrow_l * 128 + ((cA ^ qsw) << 4);
                uint32_t ab[4], asf[4];
                ldm4(sbase + qoff, ab);
                ldm4(sbase + FQ_B + qoff, asf);
#pragma unroll
                for (int p = 0; p < 4; p++) {
                    if (k0 + p * 16 <= qlim) {
                        uint32_t off = krow[p] * 128 + ((cB ^ ksw[p]) << 4);
                        uint32_t rb[4], rs[4];
                        ldm4(KbO + off, rb);
                        ldm4(KsO + off, rs);
                        mma_f16(s4[2 * p],     ab,  rb[0], rb[1]);
                        mma_f16(s4[2 * p + 1], ab,  rb[2], rb[3]);
                        mma_f16(s4[2 * p],     ab,  rs[0], rs[1]);
                        mma_f16(s4[2 * p + 1], ab,  rs[2], rs[3]);
                        mma_f16(s4[2 * p],     asf, rb[0], rb[1]);
                        mma_f16(s4[2 * p + 1], asf, rb[2], rb[3]);
                    }
                }
            }

            // ---- scale + causal mask ----
#pragma unroll
            for (int j = 0; j < 8; j++)
#pragma unroll
                for (int e = 0; e < 4; e++) s4[j][e] *= 0.125f;
            if (k0 + 63 > q0 + 16 * w) {
#pragma unroll
                for (int nt = 0; nt < 8; nt++) {
                    int kg = k0 + nt * 8 + 2 * t4;
#pragma unroll
                    for (int e = 0; e < 4; e++) {
                        int kk = kg + (e & 1);
                        int qq = qrow0 + ((e >> 1) << 3);
                        if (kk > qq) s4[nt][e] = -1e30f;
                    }
                }
            }

            // ---- online softmax ----
            float mx0 = -1e30f, mx1 = -1e30f;
#pragma unroll
            for (int j = 0; j < 8; j++) {
                mx0 = fmaxf(mx0, fmaxf(s4[j][0], s4[j][1]));
                mx1 = fmaxf(mx1, fmaxf(s4[j][2], s4[j][3]));
            }
            mx0 = fmaxf(mx0, __shfl_xor_sync(0xffffffffu, mx0, 1));
            mx0 = fmaxf(mx0, __shfl_xor_sync(0xffffffffu, mx0, 2));
            mx1 = fmaxf(mx1, __shfl_xor_sync(0xffffffffu, mx1, 1));
            mx1 = fmaxf(mx1, __shfl_xor_sync(0xffffffffu, mx1, 2));
            float mn0 = fmaxf(m0, mx0), mn1 = fmaxf(m1, mx1);
            float c0 = __expf(m0 - mn0), c1 = __expf(m1 - mn1);
            m0 = mn0; m1 = mn1;
            float sum0 = 0.0f, sum1 = 0.0f;
#pragma unroll
            for (int j = 0; j < 8; j++) {
                s4[j][0] = __expf(s4[j][0] - mn0); sum0 += s4[j][0];
                s4[j][1] = __expf(s4[j][1] - mn0); sum0 += s4[j][1];
                s4[j][2] = __expf(s4[j][2] - mn1); sum1 += s4[j][2];
                s4[j][3] = __expf(s4[j][3] - mn1); sum1 += s4[j][3];
            }
            sum0 += __shfl_xor_sync(0xffffffffu, sum0, 1);
            sum0 += __shfl_xor_sync(0xffffffffu, sum0, 2);
            sum1 += __shfl_xor_sync(0xffffffffu, sum1, 1);
            sum1 += __shfl_xor_sync(0xffffffffu, sum1, 2);
            l0 = l0 * c0 + sum0;
            l1 = l1 * c1 + sum1;
#pragma unroll
            for (int j = 0; j < 8; j++) {
                y[j][0] *= c0; y[j][1] *= c0;
                y[j][2] *= c1; y[j][3] *= c1;
            }

            // ---- Y += P V : P single fp16, V single fp16 ----
#pragma unroll
            for (int kk = 0; kk < 4; kk++) {
                if (k0 + kk * 16 <= qlim) {
                    uint32_t pab[4] = {
                        packh(s4[2 * kk][0],     s4[2 * kk][1]),
                        packh(s4[2 * kk][2],     s4[2 * kk][3]),
                        packh(s4[2 * kk + 1][0], s4[2 * kk + 1][1]),
                        packh(s4[2 * kk + 1][2], s4[2 * kk + 1][3]) };
                    const int cV = kk * 2 + (m_ & 1);
#pragma unroll
                    for (int p = 0; p < 4; p++) {
                        uint32_t off = krow[p] * 128 + ((cV ^ ksw[p]) << 4);
                        uint32_t rv[4];
                        ldm4(VhO + off, rv);
                        mma_f16(y[2 * p],     pab, rv[0], rv[1]);
                        mma_f16(y[2 * p + 1], pab, rv[2], rv[3]);
                    }
                }
            }
        }
        __syncthreads();
    }

    // ---- normalize + write single-fp16 y ----
    float inv0 = 1.0f / l0, inv1 = 1.0f / l1;
    const size_t row0 = (size_t)b * SS + q0 + 16 * w + g;
    const size_t row1 = row0 + 8;
#pragma unroll
    for (int nd = 0; nd < 8; nd++) {
        int col = h * 64 + nd * 8 + 2 * t4;
        *(uint32_t*)&g_yh[row0 * EE + col] = packh(y[nd][0] * inv0, y[nd][1] * inv0);
        *(uint32_t*)&g_yh[row1 * EE + col] = packh(y[nd][2] * inv1, y[nd][3] * inv1);
    }
}

// ---------------------------------------------------------------------------
extern "C" void kernel_launch(void* const* d_in, const int* in_sizes, int n_in,
                              void* d_out, int out_size)
{
    const float* x      = (const float*)d_in[0];
    const float* w_attn = (const float*)d_in[1];
    const float* w_proj = (const float*)d_in[2];
    float* out = (float*)d_out;

    __half *xh, *xs2, *wah, *wph, *yh;
    cudaGetSymbolAddress((void**)&xh,  g_xh);
    cudaGetSymbolAddress((void**)&xs2, g_xs2);
    cudaGetSymbolAddress((void**)&wah, g_wah);
    cudaGetSymbolAddress((void**)&wph, g_wph);
    cudaGetSymbolAddress((void**)&yh,  g_yh);

    cudaFuncSetAttribute(h_gemm_qkv, cudaFuncAttributeMaxDynamicSharedMemorySize, GEMM_DSMEM);
    cudaFuncSetAttribute(h_gemm,     cudaFuncAttributeMaxDynamicSharedMemorySize, HG_DSMEM);
    cudaFuncSetAttribute(flash_tc,   cudaFuncAttributeMaxDynamicSharedMemorySize, FLASH_SMEM);

    // 0. split x (fp16 2-term); transpose weights (single fp16)
    {
        int n4 = M_TOT * EE / 4;
        split_h_kernel<<<(n4 + 255) / 256, 256>>>(x, xh, xs2, n4);
        dim3 tb(32, 8);
        transpose_h_kernel<<<dim3(3 * EE / 32, EE / 32), tb>>>(w_attn, wah, EE, 3 * EE);
        transpose_h_kernel<<<dim3(EE / 32, EE / 32), tb>>>(w_proj, wph, EE, EE);
    }

    // 1. QKV GEMM (uniform 2-mma) -> fp16 2-term q/k + single fp16 v
    {
        dim3 grid(3 * EE / 128, M_TOT / 128);   // (24, 64)
        h_gemm_qkv<<<grid, 256, GEMM_DSMEM>>>(xh, xs2, wah);
    }

    // 2. flash attention -> single fp16 y
    {
        dim3 grid(SS / 128, BB * HH);           // (16, 64)
        flash_tc<<<grid, 256, FLASH_SMEM>>>();
    }

    // 3. proj GEMM (single fp16) -> out (fp32)
    {
        dim3 grid(EE / 128, M_TOT / 128);       // (8, 64)
        h_gemm<<<grid, 256, HG_DSMEM>>>(yh, wph, out, EE);
    }
}

// round 15
// speedup vs baseline: 1.5314x; 1.5314x over previous
#include <cuda_runtime.h>
#include <cuda_bf16.h>
#include <cuda_fp16.h>
#include <cstdint>

#define BB 4
#define SS 2048
#define EE 1024
#define HH 16
#define DD 64
#define M_TOT (BB * SS)     // 8192
#define KDIM EE             // GEMM K = 1024

// operands (all fp16)  — A/A re-bench of R14 (DVFS control run)
__device__ __half g_xh[M_TOT * EE],   g_xs2[M_TOT * EE];          // x 2-term fp16 [M][K]
__device__ __half g_wah[3 * EE * EE];                             // w_attn single fp16 [N][K]
__device__ __half g_wph[EE * EE];                                 // w_proj single fp16 [N][K]
__device__ __half g_qh[BB * HH * SS * DD], g_qs2[BB * HH * SS * DD]; // q 2-term fp16 [b,h,s,d]
__device__ __half g_kh[BB * HH * SS * DD], g_ks2[BB * HH * SS * DD]; // k 2-term fp16 [b,h,s,d]
__device__ __half g_vh[BB * HH * DD * SS];                        // v single fp16 [b,h,d,s]
__device__ __half g_yh[M_TOT * EE];                               // y single fp16 [M][E]

// ---------------------------------------------------------------------------
// Helpers
// ---------------------------------------------------------------------------
__device__ __forceinline__ uint32_t sm2u32(const void* p) {
    uint32_t a;
    asm("{ .reg .u64 t; cvta.to.shared.u64 t, %1; cvt.u32.u64 %0, t; }"
        : "=r"(a) : "l"(p));
    return a;
}

__device__ __forceinline__ uint32_t packh(float lo, float hi) {
    uint32_t r;
    asm("cvt.rn.f16x2.f32 %0, %1, %2;" : "=r"(r) : "f"(hi), "f"(lo));
    return r;
}

__device__ __forceinline__ void mma_f16(float* c, const uint32_t* a,
                                        uint32_t b0, uint32_t b1) {
    asm volatile(
        "mma.sync.aligned.m16n8k16.row.col.f32.f16.f16.f32 "
        "{%0,%1,%2,%3}, {%4,%5,%6,%7}, {%8,%9}, {%0,%1,%2,%3};\n"
        : "+f"(c[0]), "+f"(c[1]), "+f"(c[2]), "+f"(c[3])
        : "r"(a[0]), "r"(a[1]), "r"(a[2]), "r"(a[3]), "r"(b0), "r"(b1));
}

__device__ __forceinline__ void ldm4(uint32_t addr, uint32_t* r) {
    asm volatile("ldmatrix.sync.aligned.m8n8.x4.shared.b16 {%0,%1,%2,%3}, [%4];"
                 : "=r"(r[0]), "=r"(r[1]), "=r"(r[2]), "=r"(r[3]) : "r"(addr));
}

#define CP16(dst, src) \
    asm volatile("cp.async.cg.shared.global [%0], [%1], 16;" :: "r"(dst), "l"(src))
#define CP_COMMIT() asm volatile("cp.async.commit_group;")

// ---------------------------------------------------------------------------
// Prep kernels
// ---------------------------------------------------------------------------
__global__ void split_h_kernel(const float* __restrict__ in,
                               __half* __restrict__ ob,
                               __half* __restrict__ os, int n4)
{
    int i = blockIdx.x * blockDim.x + threadIdx.x;
    if (i >= n4) return;
    float4 v = ((const float4*)in)[i];
    float f[4] = {v.x, v.y, v.z, v.w};
    uint2 pb, ps;
    __half* bb = (__half*)&pb;
    __half* ss = (__half*)&ps;
#pragma unroll
    for (int e = 0; e < 4; e++) {
        __half b = __float2half_rn(f[e]);
        bb[e] = b;
        ss[e] = __float2half_rn(f[e] - __half2float(b));
    }
    ((uint2*)ob)[i] = pb;
    ((uint2*)os)[i] = ps;
}

// w[K,N] fp32 -> oh [N,K] single fp16
__global__ void transpose_h_kernel(const float* __restrict__ w,
                                   __half* __restrict__ oh, int K, int N)
{
    __shared__ float t[32][33];
    int n0 = blockIdx.x * 32, k0 = blockIdx.y * 32;
    int tx = threadIdx.x, ty = threadIdx.y;
#pragma unroll
    for (int i = 0; i < 4; i++)
        t[ty + i * 8][tx] = w[(size_t)(k0 + ty + i * 8) * N + n0 + tx];
    __syncthreads();
#pragma unroll
    for (int i = 0; i < 4; i++) {
        int n = ty + i * 8;
        oh[(size_t)(n0 + n) * K + k0 + tx] = __float2half_rn(t[tx][n]);
    }
}

// ---------------------------------------------------------------------------
// QKV GEMM: uniform 2-mma fp16: acc += (xb + xs) * wb. Block 128x128, warp
// tile 64x32, occ 2, KT=32, 3-stage cp.async pipeline (24KB stages).
// ---------------------------------------------------------------------------
#define GKT 32
#define NKT (KDIM / GKT)           // 32
#define GARR_B 8192                // 128 rows * 64 B
#define GSTAGE_B (3 * GARR_B)      // 24576
#define GEMM_DSMEM (3 * GSTAGE_B)  // 73728

__global__ __launch_bounds__(256, 2) void h_gemm_qkv(
    const __half* __restrict__ Ab, const __half* __restrict__ As_,
    const __half* __restrict__ Btb)
{
    extern __shared__ uint32_t sw4[];
    const uint32_t sbase = sm2u32(sw4);

    const int tid  = threadIdx.x;
    const int lane = tid & 31;
    const int g    = lane >> 2;
    const int t4   = lane & 3;
    const int m_   = lane >> 3;
    const int j_   = lane & 7;
    const int warp = tid >> 5;
    const int wm   = warp & 1;
    const int wn   = warp >> 1;
    const int m0   = blockIdx.y * 128;
    const int n0   = blockIdx.x * 128;

    const char* srcs[3] = {
        (const char*)(Ab  + (size_t)m0 * KDIM),
        (const char*)(As_ + (size_t)m0 * KDIM),
        (const char*)(Btb + (size_t)n0 * KDIM) };

    int arow[4], asw[4];
#pragma unroll
    for (int mt = 0; mt < 4; mt++) {
        arow[mt] = wm * 64 + mt * 16 + ((m_ & 1) << 3) + j_;
        asw[mt]  = (arow[mt] >> 1) & 3;
    }
    int brow[2], bsw[2];
#pragma unroll
    for (int p = 0; p < 2; p++) {
        brow[p] = wn * 32 + p * 16 + ((m_ >> 1) << 3) + j_;
        bsw[p]  = (brow[p] >> 1) & 3;
    }

    float acc[4][4][4];
#pragma unroll
    for (int i = 0; i < 4; i++)
#pragma unroll
        for (int j = 0; j < 4; j++)
#pragma unroll
            for (int e = 0; e < 4; e++) acc[i][j][e] = 0.0f;

    auto load_stage = [&](int s, int kt) {
        const uint32_t stb = sbase + s * GSTAGE_B;
#pragma unroll
        for (int i = 0; i < 6; i++) {
            const int arr = i >> 1;
            int local = ((i & 1) << 8) + tid;       // 0..511
            int row = local >> 2;
            int c   = local & 3;
            uint32_t dst = stb + arr * GARR_B + row * 64 +
                           ((c ^ ((row >> 1) & 3)) << 4);
            const char* src = srcs[arr] + (size_t)row * (KDIM * 2) + kt * 64 + c * 16;
            CP16(dst, src);
        }
        CP_COMMIT();
    };

    load_stage(0, 0);
    load_stage(1, 1);

    for (int kt = 0; kt < NKT; kt++) {
        const int s = kt % 3;
        if (kt + 1 < NKT) {
            asm volatile("cp.async.wait_group 1;");
        } else {
            asm volatile("cp.async.wait_group 0;");
        }
        __syncthreads();
        if (kt + 2 < NKT) load_stage((kt + 2) % 3, kt + 2);

        const uint32_t AbO = sbase + s * GSTAGE_B;
        const uint32_t AsO = AbO + GARR_B;
        const uint32_t BbO = AbO + 2 * GARR_B;

#pragma unroll
        for (int ks = 0; ks < 2; ks++) {
            const int cA = ks * 2 + (m_ >> 1);
            const int cB = ks * 2 + (m_ & 1);

            uint32_t bb[4][2];
#pragma unroll
            for (int p = 0; p < 2; p++) {
                uint32_t off = brow[p] * 64 + ((cB ^ bsw[p]) << 4);
                uint32_t r[4];
                ldm4(BbO + off, r);
                bb[2 * p][0] = r[0];     bb[2 * p][1] = r[1];
                bb[2 * p + 1][0] = r[2]; bb[2 * p + 1][1] = r[3];
            }
#pragma unroll
            for (int mt = 0; mt < 4; mt++) {
                uint32_t off = arow[mt] * 64 + ((cA ^ asw[mt]) << 4);
                uint32_t ab[4], asf[4];
                ldm4(AbO + off, ab);
                ldm4(AsO + off, asf);
#pragma unroll
                for (int nt = 0; nt < 4; nt++)
                    mma_f16(acc[mt][nt], ab,  bb[nt][0], bb[nt][1]);
#pragma unroll
                for (int nt = 0; nt < 4; nt++)
                    mma_f16(acc[mt][nt], asf, bb[nt][0], bb[nt][1]);
            }
        }
    }

    // ---- epilogue: q/k fp16 2-term, v single fp16 transposed ----
#pragma unroll
    for (int mt = 0; mt < 4; mt++) {
#pragma unroll
        for (int nt = 0; nt < 4; nt++) {
            const int r  = m0 + wm * 64 + mt * 16 + g;
            const int cc = n0 + wn * 32 + nt * 8 + 2 * t4;
            float v0 = acc[mt][nt][0], v1 = acc[mt][nt][1];
            float v2 = acc[mt][nt][2], v3 = acc[mt][nt][3];
            const int sec = cc >> 10;
            const int c10 = cc & 1023;
            const int h   = c10 >> 6;
            const int d0  = c10 & 63;
            const int b   = r >> 11;
            const int sl  = r & 2047;
            if (sec < 2) {
                float b0 = __half2float(__float2half_rn(v0));
                float b1 = __half2float(__float2half_rn(v1));
                float b2 = __half2float(__float2half_rn(v2));
                float b3 = __half2float(__float2half_rn(v3));
                __half* dh = (sec == 0) ? g_qh  : g_kh;
                __half* ds = (sec == 0) ? g_qs2 : g_ks2;
                size_t i0 = (((size_t)(b * HH + h)) * SS + sl) * DD + d0;
                *(uint32_t*)&dh[i0] = packh(b0, b1);
                *(uint32_t*)&ds[i0] = packh(v0 - b0, v1 - b1);
                *(uint32_t*)&dh[i0 + 8 * DD] = packh(b2, b3);
                *(uint32_t*)&ds[i0 + 8 * DD] = packh(v2 - b2, v3 - b3);
            } else {
                size_t base = ((size_t)(b * HH + h)) * DD * SS;
                size_t iA = base + (size_t)d0 * SS + sl;
                size_t iB = base + (size_t)(d0 + 1) * SS + sl;
                g_vh[iA]     = __float2half_rn(v0);
                g_vh[iB]     = __float2half_rn(v1);
                g_vh[iA + 8] = __float2half_rn(v2);
                g_vh[iB + 8] = __float2half_rn(v3);
            }
        }
    }
}

// ---------------------------------------------------------------------------
// Proj GEMM: single fp16, 1 mma per acc per k-chunk.
// ---------------------------------------------------------------------------
#define HARR_B 8192
#define HSTAGE_B (2 * HARR_B)      // 16384
#define HG_DSMEM (3 * HSTAGE_B)    // 49152

__global__ __launch_bounds__(256, 2) void h_gemm(
    const __half* __restrict__ Ah, const __half* __restrict__ Bh,
    float* __restrict__ C, int Ncols)
{
    extern __shared__ uint32_t sw4[];
    const uint32_t sbase = sm2u32(sw4);

    const int tid  = threadIdx.x;
    const int lane = tid & 31;
    const int g    = lane >> 2;
    const int t4   = lane & 3;
    const int m_   = lane >> 3;
    const int j_   = lane & 7;
    const int warp = tid >> 5;
    const int wm   = warp & 1;
    const int wn   = warp >> 1;
    const int m0   = blockIdx.y * 128;
    const int n0   = blockIdx.x * 128;

    const char* srcs[2] = {
        (const char*)(Ah + (size_t)m0 * KDIM),
        (const char*)(Bh + (size_t)n0 * KDIM) };

    int arow[4], asw[4];
#pragma unroll
    for (int mt = 0; mt < 4; mt++) {
        arow[mt] = wm * 64 + mt * 16 + ((m_ & 1) << 3) + j_;
        asw[mt]  = (arow[mt] >> 1) & 3;
    }
    int brow[2], bsw[2];
#pragma unroll
    for (int p = 0; p < 2; p++) {
        brow[p] = wn * 32 + p * 16 + ((m_ >> 1) << 3) + j_;
        bsw[p]  = (brow[p] >> 1) & 3;
    }

    float acc[4][4][4];
#pragma unroll
    for (int i = 0; i < 4; i++)
#pragma unroll
        for (int j = 0; j < 4; j++)
#pragma unroll
            for (int e = 0; e < 4; e++) acc[i][j][e] = 0.0f;

    auto load_stage = [&](int s, int kt) {
        const uint32_t stb = sbase + s * HSTAGE_B;
#pragma unroll
        for (int i = 0; i < 4; i++) {
            const int arr = i >> 1;
            int local = ((i & 1) << 8) + tid;
            int row = local >> 2;
            int c   = local & 3;
            uint32_t dst = stb + arr * HARR_B + row * 64 +
                           ((c ^ ((row >> 1) & 3)) << 4);
            const char* src = srcs[arr] + (size_t)row * (KDIM * 2) + kt * 64 + c * 16;
            CP16(dst, src);
        }
        CP_COMMIT();
    };

    load_stage(0, 0);
    load_stage(1, 1);

    for (int kt = 0; kt < NKT; kt++) {
        const int s = kt % 3;
        if (kt + 1 < NKT) {
            asm volatile("cp.async.wait_group 1;");
        } else {
            asm volatile("cp.async.wait_group 0;");
        }
        __syncthreads();
        if (kt + 2 < NKT) load_stage((kt + 2) % 3, kt + 2);

        const uint32_t AO = sbase + s * HSTAGE_B;
        const uint32_t BO = AO + HARR_B;

#pragma unroll
        for (int ks = 0; ks < 2; ks++) {
            const int cA = ks * 2 + (m_ >> 1);
            const int cB = ks * 2 + (m_ & 1);

            uint32_t bb[4][2];
#pragma unroll
            for (int p = 0; p < 2; p++) {
                uint32_t off = brow[p] * 64 + ((cB ^ bsw[p]) << 4);
                uint32_t r[4];
                ldm4(BO + off, r);
                bb[2 * p][0] = r[0];     bb[2 * p][1] = r[1];
                bb[2 * p + 1][0] = r[2]; bb[2 * p + 1][1] = r[3];
            }
#pragma unroll
            for (int mt = 0; mt < 4; mt++) {
                uint32_t off = arow[mt] * 64 + ((cA ^ asw[mt]) << 4);
                uint32_t ab[4];
                ldm4(AO + off, ab);
#pragma unroll
                for (int nt = 0; nt < 4; nt++)
                    mma_f16(acc[mt][nt], ab, bb[nt][0], bb[nt][1]);
            }
        }
    }

#pragma unroll
    for (int mt = 0; mt < 4; mt++) {
#pragma unroll
        for (int nt = 0; nt < 4; nt++) {
            const int r  = m0 + wm * 64 + mt * 16 + g;
            const int cc = n0 + wn * 32 + nt * 8 + 2 * t4;
            size_t i0 = (size_t)r * Ncols + cc;
            *(float2*)&C[i0] = make_float2(acc[mt][nt][0], acc[mt][nt][1]);
            *(float2*)&C[i0 + (size_t)8 * Ncols] =
                make_float2(acc[mt][nt][2], acc[mt][nt][3]);
        }
    }
}

// ---------------------------------------------------------------------------
// Tensor-core flash attention. QK^T: 3-term fp16. PV: single fp16 (2 mmas/
// chunk). y single fp16. Double-buffered 24KB K/V stages, causal skip.
// ---------------------------------------------------------------------------
#define FQ_B   16384
#define FARR_B 8192
#define FSTAGE_B (3 * FARR_B)                  // Kh,Ks2,Vh = 24576
#define FLASH_SMEM (2 * FQ_B + 2 * FSTAGE_B)   // 81920

__global__ __launch_bounds__(256, 2) void flash_tc(void)
{
    extern __shared__ uint32_t fw4[];
    const uint32_t sbase = sm2u32(fw4);

    const int tid  = threadIdx.x;
    const int lane = tid & 31;
    const int g    = lane >> 2;
    const int t4   = lane & 3;
    const int m_   = lane >> 3;
    const int j_   = lane & 7;
    const int w    = tid >> 5;
    const int qt   = (int)gridDim.x - 1 - (int)blockIdx.x;  // longest-first
    const int bh   = blockIdx.y;
    const int q0   = qt * 128;
    const int b    = bh >> 4, h = bh & 15;

    const char* qb_src = (const char*)(g_qh  + ((size_t)bh * SS + q0) * DD);
    const char* qs_src = (const char*)(g_qs2 + ((size_t)bh * SS + q0) * DD);
    const char* kb_base = (const char*)(g_kh  + (size_t)bh * SS * DD);
    const char* ks_base = (const char*)(g_ks2 + (size_t)bh * SS * DD);
    const char* vh_base = (const char*)(g_vh  + (size_t)bh * DD * SS);

    const int qrow_l = 16 * w + ((m_ & 1) << 3) + j_;
    const int qsw    = qrow_l & 7;
    int krow[4], ksw[4];
#pragma unroll
    for (int p = 0; p < 4; p++) {
        krow[p] = p * 16 + ((m_ >> 1) << 3) + j_;
        ksw[p]  = krow[p] & 7;
    }

    // ---- prologue loads: Q (2 arrays) + KV stage 0 (3 arrays) ----
#pragma unroll
    for (int i = 0; i < 8; i++) {
        const int arr = i >> 2;
        int local = ((i & 3) << 8) + tid;
        int row = local >> 3, c = local & 7;
        uint32_t dst = sbase + arr * FQ_B + row * 128 + ((c ^ (row & 7)) << 4);
        const char* src = (arr ? qs_src : qb_src) + (size_t)row * 128 + c * 16;
        CP16(dst, src);
    }
#pragma unroll
    for (int i = 0; i < 6; i++) {
        const int arr = i >> 1;
        int local = ((i & 1) << 8) + tid;
        int row = local >> 3, c = local & 7;
        uint32_t dst = sbase + 2 * FQ_B + arr * FARR_B + row * 128 +
                       ((c ^ (row & 7)) << 4);
        const char* src;
        if (arr == 0)      src = kb_base + (size_t)row * 128 + c * 16;
        else if (arr == 1) src = ks_base + (size_t)row * 128 + c * 16;
        else               src = vh_base + (size_t)row * (SS * 2) + c * 16;
        CP16(dst, src);
    }
    CP_COMMIT();

    float s4[8][4], y[8][4];
#pragma unroll
    for (int j = 0; j < 8; j++)
#pragma unroll
        for (int e = 0; e < 4; e++) y[j][e] = 0.0f;
    float m0 = -1e30f, m1 = -1e30f, l0 = 0.0f, l1 = 0.0f;

    const int qrow0 = q0 + 16 * w + g;
    const int qlim  = q0 + 16 * w + 15;
    const int jmax  = 2 * qt + 2;

    for (int jt = 0; jt < jmax; jt++) {
        const int s  = jt & 1;
        const int k0 = jt * 64;

        if (jt + 1 < jmax) {
            const int kn = (jt + 1) * 64;
            const uint32_t stb = sbase + 2 * FQ_B + (s ^ 1) * FSTAGE_B;
#pragma unroll
            for (int i = 0; i < 6; i++) {
                const int arr = i >> 1;
                int local = ((i & 1) << 8) + tid;
                int row = local >> 3, c = local & 7;
                uint32_t dst = stb + arr * FARR_B + row * 128 + ((c ^ (row & 7)) << 4);
                const char* src;
                if (arr == 0)      src = kb_base + ((size_t)(kn + row)) * 128 + c * 16;
                else if (arr == 1) src = ks_base + ((size_t)(kn + row)) * 128 + c * 16;
                else               src = vh_base + (size_t)row * (SS * 2) + kn * 2 + c * 16;
                CP16(dst, src);
            }
            CP_COMMIT();
            asm volatile("cp.async.wait_group 1;");
        } else {
            asm volatile("cp.async.wait_group 0;");
        }
        __syncthreads();

        const bool active = (k0 <= qlim);
        if (active) {
            const uint32_t KbO = sbase + 2 * FQ_B + s * FSTAGE_B;
            const uint32_t KsO = KbO + FARR_B;
            const uint32_t VhO = KbO + 2 * FARR_B;

            // ---- S = Q K^T (3-term fp16, causal skip per 16-key pair) ----
#pragma unroll
            for (int j = 0; j < 8; j++)
#pragma unroll
                for (int e = 0; e < 4; e++) s4[j][e] = 0.0f;

#pragma unroll
            for (int ks = 0; ks < 4; ks++) {
                const int cA = ks * 2 + (m_ >> 1);
                const int cB = ks * 2 + (m_ & 1);
                uint32_t qoff = qrow_l * 128 + ((cA ^ qsw) << 4);
                uint32_t ab[4], asf[4];
                ldm4(sbase + qoff, ab);
                ldm4(sbase + FQ_B + qoff, asf);
#pragma unroll
                for (int p = 0; p < 4; p++) {
                    if (k0 + p * 16 <= qlim) {
                        uint32_t off = krow[p] * 128 + ((cB ^ ksw[p]) << 4);
                        uint32_t rb[4], rs[4];
                        ldm4(KbO + off, rb);
                        ldm4(KsO + off, rs);
                        mma_f16(s4[2 * p],     ab,  rb[0], rb[1]);
                        mma_f16(s4[2 * p + 1], ab,  rb[2], rb[3]);
                        mma_f16(s4[2 * p],     ab,  rs[0], rs[1]);
                        mma_f16(s4[2 * p + 1], ab,  rs[2], rs[3]);
                        mma_f16(s4[2 * p],     asf, rb[0], rb[1]);
                        mma_f16(s4[2 * p + 1], asf, rb[2], rb[3]);
                    }
                }
            }

            // ---- scale + causal mask ----
#pragma unroll
            for (int j = 0; j < 8; j++)
#pragma unroll
                for (int e = 0; e < 4; e++) s4[j][e] *= 0.125f;
            if (k0 + 63 > q0 + 16 * w) {
#pragma unroll
                for (int nt = 0; nt < 8; nt++) {
                    int kg = k0 + nt * 8 + 2 * t4;
#pragma unroll
                    for (int e = 0; e < 4; e++) {
                        int kk = kg + (e & 1);
                        int qq = qrow0 + ((e >> 1) << 3);
                        if (kk > qq) s4[nt][e] = -1e30f;
                    }
                }
            }

            // ---- online softmax ----
            float mx0 = -1e30f, mx1 = -1e30f;
#pragma unroll
            for (int j = 0; j < 8; j++) {
                mx0 = fmaxf(mx0, fmaxf(s4[j][0], s4[j][1]));
                mx1 = fmaxf(mx1, fmaxf(s4[j][2], s4[j][3]));
            }
            mx0 = fmaxf(mx0, __shfl_xor_sync(0xffffffffu, mx0, 1));
            mx0 = fmaxf(mx0, __shfl_xor_sync(0xffffffffu, mx0, 2));
            mx1 = fmaxf(mx1, __shfl_xor_sync(0xffffffffu, mx1, 1));
            mx1 = fmaxf(mx1, __shfl_xor_sync(0xffffffffu, mx1, 2));
            float mn0 = fmaxf(m0, mx0), mn1 = fmaxf(m1, mx1);
            float c0 = __expf(m0 - mn0), c1 = __expf(m1 - mn1);
            m0 = mn0; m1 = mn1;
            float sum0 = 0.0f, sum1 = 0.0f;
#pragma unroll
            for (int j = 0; j < 8; j++) {
                s4[j][0] = __expf(s4[j][0] - mn0); sum0 += s4[j][0];
                s4[j][1] = __expf(s4[j][1] - mn0); sum0 += s4[j][1];
                s4[j][2] = __expf(s4[j][2] - mn1); sum1 += s4[j][2];
                s4[j][3] = __expf(s4[j][3] - mn1); sum1 += s4[j][3];
            }
            sum0 += __shfl_xor_sync(0xffffffffu, sum0, 1);
            sum0 += __shfl_xor_sync(0xffffffffu, sum0, 2);
            sum1 += __shfl_xor_sync(0xffffffffu, sum1, 1);
            sum1 += __shfl_xor_sync(0xffffffffu, sum1, 2);
            l0 = l0 * c0 + sum0;
            l1 = l1 * c1 + sum1;
#pragma unroll
            for (int j = 0; j < 8; j++) {
                y[j][0] *= c0; y[j][1] *= c0;
                y[j][2] *= c1; y[j][3] *= c1;
            }

            // ---- Y += P V : P single fp16, V single fp16 ----
#pragma unroll
            for (int kk = 0; kk < 4; kk++) {
                if (k0 + kk * 16 <= qlim) {
                    uint32_t pab[4] = {
                        packh(s4[2 * kk][0],     s4[2 * kk][1]),
                        packh(s4[2 * kk][2],     s4[2 * kk][3]),
                        packh(s4[2 * kk + 1][0], s4[2 * kk + 1][1]),
                        packh(s4[2 * kk + 1][2], s4[2 * kk + 1][3]) };
                    const int cV = kk * 2 + (m_ & 1);
#pragma unroll
                    for (int p = 0; p < 4; p++) {
                        uint32_t off = krow[p] * 128 + ((cV ^ ksw[p]) << 4);
                        uint32_t rv[4];
                        ldm4(VhO + off, rv);
                        mma_f16(y[2 * p],     pab, rv[0], rv[1]);
                        mma_f16(y[2 * p + 1], pab, rv[2], rv[3]);
                    }
                }
            }
        }
        __syncthreads();
    }

    // ---- normalize + write single-fp16 y ----
    float inv0 = 1.0f / l0, inv1 = 1.0f / l1;
    const size_t row0 = (size_t)b * SS + q0 + 16 * w + g;
    const size_t row1 = row0 + 8;
#pragma unroll
    for (int nd = 0; nd < 8; nd++) {
        int col = h * 64 + nd * 8 + 2 * t4;
        *(uint32_t*)&g_yh[row0 * EE + col] = packh(y[nd][0] * inv0, y[nd][1] * inv0);
        *(uint32_t*)&g_yh[row1 * EE + col] = packh(y[nd][2] * inv1, y[nd][3] * inv1);
    }
}

// ---------------------------------------------------------------------------
extern "C" void kernel_launch(void* const* d_in, const int* in_sizes, int n_in,
                              void* d_out, int out_size)
{
    const float* x      = (const float*)d_in[0];
    const float* w_attn = (const float*)d_in[1];
    const float* w_proj = (const float*)d_in[2];
    float* out = (float*)d_out;

    __half *xh, *xs2, *wah, *wph, *yh;
    cudaGetSymbolAddress((void**)&xh,  g_xh);
    cudaGetSymbolAddress((void**)&xs2, g_xs2);
    cudaGetSymbolAddress((void**)&wah, g_wah);
    cudaGetSymbolAddress((void**)&wph, g_wph);
    cudaGetSymbolAddress((void**)&yh,  g_yh);

    cudaFuncSetAttribute(h_gemm_qkv, cudaFuncAttributeMaxDynamicSharedMemorySize, GEMM_DSMEM);
    cudaFuncSetAttribute(h_gemm,     cudaFuncAttributeMaxDynamicSharedMemorySize, HG_DSMEM);
    cudaFuncSetAttribute(flash_tc,   cudaFuncAttributeMaxDynamicSharedMemorySize, FLASH_SMEM);

    // 0. split x (fp16 2-term); transpose weights (single fp16)
    {
        int n4 = M_TOT * EE / 4;
        split_h_kernel<<<(n4 + 255) / 256, 256>>>(x, xh, xs2, n4);
        dim3 tb(32, 8);
        transpose_h_kernel<<<dim3(3 * EE / 32, EE / 32), tb>>>(w_attn, wah, EE, 3 * EE);
        transpose_h_kernel<<<dim3(EE / 32, EE / 32), tb>>>(w_proj, wph, EE, EE);
    }

    // 1. QKV GEMM (uniform 2-mma) -> fp16 2-term q/k + single fp16 v
    {
        dim3 grid(3 * EE / 128, M_TOT / 128);   // (24, 64)
        h_gemm_qkv<<<grid, 256, GEMM_DSMEM>>>(xh, xs2, wah);
    }

    // 2. flash attention -> single fp16 y
    {
        dim3 grid(SS / 128, BB * HH);           // (16, 64)
        flash_tc<<<grid, 256, FLASH_SMEM>>>();
    }

    // 3. proj GEMM (single fp16) -> out (fp32)
    {
        dim3 grid(EE / 128, M_TOT / 128);       // (8, 64)
        h_gemm<<<grid, 256, HG_DSMEM>>>(yh, wph, out, EE);
    }
}

// round 16
// speedup vs baseline: 2.0709x; 1.3523x over previous
#include <cuda_runtime.h>
#include <cuda_bf16.h>
#include <cuda_fp16.h>
#include <cstdint>

#define BB 4
#define SS 2048
#define EE 1024
#define HH 16
#define DD 64
#define M_TOT (BB * SS)     // 8192
#define KDIM EE             // GEMM K = 1024

// operands (fp16)
__device__ __half g_xh[M_TOT * EE];                               // x single fp16 [M][K]
__device__ __half g_wah[3 * EE * EE];                             // w_attn single fp16 [N][K]
__device__ __half g_wph[EE * EE];                                 // w_proj single fp16 [N][K]
__device__ __half g_qh[BB * HH * SS * DD], g_qs2[BB * HH * SS * DD]; // q 2-term fp16 [b,h,s,d]
__device__ __half g_kh[BB * HH * SS * DD];                        // k single fp16 [b,h,s,d]
__device__ __half g_vh[BB * HH * DD * SS];                        // v single fp16 [b,h,d,s]
__device__ __half g_yh[M_TOT * EE];                               // y single fp16 [M][E]

// ---------------------------------------------------------------------------
// Helpers
// ---------------------------------------------------------------------------
__device__ __forceinline__ uint32_t sm2u32(const void* p) {
    uint32_t a;
    asm("{ .reg .u64 t; cvta.to.shared.u64 t, %1; cvt.u32.u64 %0, t; }"
        : "=r"(a) : "l"(p));
    return a;
}

__device__ __forceinline__ uint32_t packh(float lo, float hi) {
    uint32_t r;
    asm("cvt.rn.f16x2.f32 %0, %1, %2;" : "=r"(r) : "f"(hi), "f"(lo));
    return r;
}

__device__ __forceinline__ void mma_f16(float* c, const uint32_t* a,
                                        uint32_t b0, uint32_t b1) {
    asm volatile(
        "mma.sync.aligned.m16n8k16.row.col.f32.f16.f16.f32 "
        "{%0,%1,%2,%3}, {%4,%5,%6,%7}, {%8,%9}, {%0,%1,%2,%3};\n"
        : "+f"(c[0]), "+f"(c[1]), "+f"(c[2]), "+f"(c[3])
        : "r"(a[0]), "r"(a[1]), "r"(a[2]), "r"(a[3]), "r"(b0), "r"(b1));
}

__device__ __forceinline__ void ldm4(uint32_t addr, uint32_t* r) {
    asm volatile("ldmatrix.sync.aligned.m8n8.x4.shared.b16 {%0,%1,%2,%3}, [%4];"
                 : "=r"(r[0]), "=r"(r[1]), "=r"(r[2]), "=r"(r[3]) : "r"(addr));
}

#define CP16(dst, src) \
    asm volatile("cp.async.cg.shared.global [%0], [%1], 16;" :: "r"(dst), "l"(src))
#define CP_COMMIT() asm volatile("cp.async.commit_group;")

// ---------------------------------------------------------------------------
// Prep kernels
// ---------------------------------------------------------------------------
// fp32 -> single fp16
__global__ void convert_h_kernel(const float* __restrict__ in,
                                 __half* __restrict__ oh, int n4)
{
    int i = blockIdx.x * blockDim.x + threadIdx.x;
    if (i >= n4) return;
    float4 v = ((const float4*)in)[i];
    uint2 p;
    ((uint32_t*)&p)[0] = packh(v.x, v.y);
    ((uint32_t*)&p)[1] = packh(v.z, v.w);
    ((uint2*)oh)[i] = p;
}

// w[K,N] fp32 -> oh [N,K] single fp16
__global__ void transpose_h_kernel(const float* __restrict__ w,
                                   __half* __restrict__ oh, int K, int N)
{
    __shared__ float t[32][33];
    int n0 = blockIdx.x * 32, k0 = blockIdx.y * 32;
    int tx = threadIdx.x, ty = threadIdx.y;
#pragma unroll
    for (int i = 0; i < 4; i++)
        t[ty + i * 8][tx] = w[(size_t)(k0 + ty + i * 8) * N + n0 + tx];
    __syncthreads();
#pragma unroll
    for (int i = 0; i < 4; i++) {
        int n = ty + i * 8;
        oh[(size_t)(n0 + n) * K + k0 + tx] = __float2half_rn(t[tx][n]);
    }
}

// ---------------------------------------------------------------------------
// QKV GEMM: single fp16, 1 mma per acc per k-chunk. Block 128x128, warp tile
// 64x32, occ 2, KT=32, 3-stage pipeline (16KB stages: A | B).
// Epilogue: q -> fp16 2-term; k -> single fp16; v -> single fp16 transposed.
// ---------------------------------------------------------------------------
#define GKT 32
#define NKT (KDIM / GKT)           // 32
#define GARR_B 8192                // 128 rows * 64 B
#define GSTAGE_B (2 * GARR_B)      // 16384
#define GEMM_DSMEM (3 * GSTAGE_B)  // 49152

__global__ __launch_bounds__(256, 2) void h_gemm_qkv(
    const __half* __restrict__ Ah, const __half* __restrict__ Btb)
{
    extern __shared__ uint32_t sw4[];
    const uint32_t sbase = sm2u32(sw4);

    const int tid  = threadIdx.x;
    const int lane = tid & 31;
    const int g    = lane >> 2;
    const int t4   = lane & 3;
    const int m_   = lane >> 3;
    const int j_   = lane & 7;
    const int warp = tid >> 5;
    const int wm   = warp & 1;
    const int wn   = warp >> 1;
    const int m0   = blockIdx.y * 128;
    const int n0   = blockIdx.x * 128;

    const char* srcs[2] = {
        (const char*)(Ah  + (size_t)m0 * KDIM),
        (const char*)(Btb + (size_t)n0 * KDIM) };

    int arow[4], asw[4];
#pragma unroll
    for (int mt = 0; mt < 4; mt++) {
        arow[mt] = wm * 64 + mt * 16 + ((m_ & 1) << 3) + j_;
        asw[mt]  = (arow[mt] >> 1) & 3;
    }
    int brow[2], bsw[2];
#pragma unroll
    for (int p = 0; p < 2; p++) {
        brow[p] = wn * 32 + p * 16 + ((m_ >> 1) << 3) + j_;
        bsw[p]  = (brow[p] >> 1) & 3;
    }

    float acc[4][4][4];
#pragma unroll
    for (int i = 0; i < 4; i++)
#pragma unroll
        for (int j = 0; j < 4; j++)
#pragma unroll
            for (int e = 0; e < 4; e++) acc[i][j][e] = 0.0f;

    auto load_stage = [&](int s, int kt) {
        const uint32_t stb = sbase + s * GSTAGE_B;
#pragma unroll
        for (int i = 0; i < 4; i++) {
            const int arr = i >> 1;
            int local = ((i & 1) << 8) + tid;       // 0..511
            int row = local >> 2;
            int c   = local & 3;
            uint32_t dst = stb + arr * GARR_B + row * 64 +
                           ((c ^ ((row >> 1) & 3)) << 4);
            const char* src = srcs[arr] + (size_t)row * (KDIM * 2) + kt * 64 + c * 16;
            CP16(dst, src);
        }
        CP_COMMIT();
    };

    load_stage(0, 0);
    load_stage(1, 1);

    for (int kt = 0; kt < NKT; kt++) {
        const int s = kt % 3;
        if (kt + 1 < NKT) {
            asm volatile("cp.async.wait_group 1;");
        } else {
            asm volatile("cp.async.wait_group 0;");
        }
        __syncthreads();
        if (kt + 2 < NKT) load_stage((kt + 2) % 3, kt + 2);

        const uint32_t AO = sbase + s * GSTAGE_B;
        const uint32_t BO = AO + GARR_B;

#pragma unroll
        for (int ks = 0; ks < 2; ks++) {
            const int cA = ks * 2 + (m_ >> 1);
            const int cB = ks * 2 + (m_ & 1);

            uint32_t bb[4][2];
#pragma unroll
            for (int p = 0; p < 2; p++) {
                uint32_t off = brow[p] * 64 + ((cB ^ bsw[p]) << 4);
                uint32_t r[4];
                ldm4(BO + off, r);
                bb[2 * p][0] = r[0];     bb[2 * p][1] = r[1];
                bb[2 * p + 1][0] = r[2]; bb[2 * p + 1][1] = r[3];
            }
#pragma unroll
            for (int mt = 0; mt < 4; mt++) {
                uint32_t off = arow[mt] * 64 + ((cA ^ asw[mt]) << 4);
                uint32_t ab[4];
                ldm4(AO + off, ab);
#pragma unroll
                for (int nt = 0; nt < 4; nt++)
                    mma_f16(acc[mt][nt], ab, bb[nt][0], bb[nt][1]);
            }
        }
    }

    // ---- epilogue: q fp16 2-term, k single fp16, v single fp16 transposed ----
#pragma unroll
    for (int mt = 0; mt < 4; mt++) {
#pragma unroll
        for (int nt = 0; nt < 4; nt++) {
            const int r  = m0 + wm * 64 + mt * 16 + g;
            const int cc = n0 + wn * 32 + nt * 8 + 2 * t4;
            float v0 = acc[mt][nt][0], v1 = acc[mt][nt][1];
            float v2 = acc[mt][nt][2], v3 = acc[mt][nt][3];
            const int sec = cc >> 10;
            const int c10 = cc & 1023;
            const int h   = c10 >> 6;
            const int d0  = c10 & 63;
            const int b   = r >> 11;
            const int sl  = r & 2047;
            if (sec == 0) {
                float b0 = __half2float(__float2half_rn(v0));
                float b1 = __half2float(__float2half_rn(v1));
                float b2 = __half2float(__float2half_rn(v2));
                float b3 = __half2float(__float2half_rn(v3));
                size_t i0 = (((size_t)(b * HH + h)) * SS + sl) * DD + d0;
                *(uint32_t*)&g_qh[i0]  = packh(b0, b1);
                *(uint32_t*)&g_qs2[i0] = packh(v0 - b0, v1 - b1);
                *(uint32_t*)&g_qh[i0 + 8 * DD]  = packh(b2, b3);
                *(uint32_t*)&g_qs2[i0 + 8 * DD] = packh(v2 - b2, v3 - b3);
            } else if (sec == 1) {
                size_t i0 = (((size_t)(b * HH + h)) * SS + sl) * DD + d0;
                *(uint32_t*)&g_kh[i0]          = packh(v0, v1);
                *(uint32_t*)&g_kh[i0 + 8 * DD] = packh(v2, v3);
            } else {
                size_t base = ((size_t)(b * HH + h)) * DD * SS;
                size_t iA = base + (size_t)d0 * SS + sl;
                size_t iB = base + (size_t)(d0 + 1) * SS + sl;
                g_vh[iA]     = __float2half_rn(v0);
                g_vh[iB]     = __float2half_rn(v1);
                g_vh[iA + 8] = __float2half_rn(v2);
                g_vh[iB + 8] = __float2half_rn(v3);
            }
        }
    }
}

// ---------------------------------------------------------------------------
// Proj GEMM: single fp16, 1 mma per acc per k-chunk (unchanged).
// ---------------------------------------------------------------------------
#define HARR_B 8192
#define HSTAGE_B (2 * HARR_B)      // 16384
#define HG_DSMEM (3 * HSTAGE_B)    // 49152

__global__ __launch_bounds__(256, 2) void h_gemm(
    const __half* __restrict__ Ah, const __half* __restrict__ Bh,
    float* __restrict__ C, int Ncols)
{
    extern __shared__ uint32_t sw4[];
    const uint32_t sbase = sm2u32(sw4);

    const int tid  = threadIdx.x;
    const int lane = tid & 31;
    const int g    = lane >> 2;
    const int t4   = lane & 3;
    const int m_   = lane >> 3;
    const int j_   = lane & 7;
    const int warp = tid >> 5;
    const int wm   = warp & 1;
    const int wn   = warp >> 1;
    const int m0   = blockIdx.y * 128;
    const int n0   = blockIdx.x * 128;

    const char* srcs[2] = {
        (const char*)(Ah + (size_t)m0 * KDIM),
        (const char*)(Bh + (size_t)n0 * KDIM) };

    int arow[4], asw[4];
#pragma unroll
    for (int mt = 0; mt < 4; mt++) {
        arow[mt] = wm * 64 + mt * 16 + ((m_ & 1) << 3) + j_;
        asw[mt]  = (arow[mt] >> 1) & 3;
    }
    int brow[2], bsw[2];
#pragma unroll
    for (int p = 0; p < 2; p++) {
        brow[p] = wn * 32 + p * 16 + ((m_ >> 1) << 3) + j_;
        bsw[p]  = (brow[p] >> 1) & 3;
    }

    float acc[4][4][4];
#pragma unroll
    for (int i = 0; i < 4; i++)
#pragma unroll
        for (int j = 0; j < 4; j++)
#pragma unroll
            for (int e = 0; e < 4; e++) acc[i][j][e] = 0.0f;

    auto load_stage = [&](int s, int kt) {
        const uint32_t stb = sbase + s * HSTAGE_B;
#pragma unroll
        for (int i = 0; i < 4; i++) {
            const int arr = i >> 1;
            int local = ((i & 1) << 8) + tid;
            int row = local >> 2;
            int c   = local & 3;
            uint32_t dst = stb + arr * HARR_B + row * 64 +
                           ((c ^ ((row >> 1) & 3)) << 4);
            const char* src = srcs[arr] + (size_t)row * (KDIM * 2) + kt * 64 + c * 16;
            CP16(dst, src);
        }
        CP_COMMIT();
    };

    load_stage(0, 0);
    load_stage(1, 1);

    for (int kt = 0; kt < NKT; kt++) {
        const int s = kt % 3;
        if (kt + 1 < NKT) {
            asm volatile("cp.async.wait_group 1;");
        } else {
            asm volatile("cp.async.wait_group 0;");
        }
        __syncthreads();
        if (kt + 2 < NKT) load_stage((kt + 2) % 3, kt + 2);

        const uint32_t AO = sbase + s * HSTAGE_B;
        const uint32_t BO = AO + HARR_B;

#pragma unroll
        for (int ks = 0; ks < 2; ks++) {
            const int cA = ks * 2 + (m_ >> 1);
            const int cB = ks * 2 + (m_ & 1);

            uint32_t bb[4][2];
#pragma unroll
            for (int p = 0; p < 2; p++) {
                uint32_t off = brow[p] * 64 + ((cB ^ bsw[p]) << 4);
                uint32_t r[4];
                ldm4(BO + off, r);
                bb[2 * p][0] = r[0];     bb[2 * p][1] = r[1];
                bb[2 * p + 1][0] = r[2]; bb[2 * p + 1][1] = r[3];
            }
#pragma unroll
            for (int mt = 0; mt < 4; mt++) {
                uint32_t off = arow[mt] * 64 + ((cA ^ asw[mt]) << 4);
                uint32_t ab[4];
                ldm4(AO + off, ab);
#pragma unroll
                for (int nt = 0; nt < 4; nt++)
                    mma_f16(acc[mt][nt], ab, bb[nt][0], bb[nt][1]);
            }
        }
    }

#pragma unroll
    for (int mt = 0; mt < 4; mt++) {
#pragma unroll
        for (int nt = 0; nt < 4; nt++) {
            const int r  = m0 + wm * 64 + mt * 16 + g;
            const int cc = n0 + wn * 32 + nt * 8 + 2 * t4;
            size_t i0 = (size_t)r * Ncols + cc;
            *(float2*)&C[i0] = make_float2(acc[mt][nt][0], acc[mt][nt][1]);
            *(float2*)&C[i0 + (size_t)8 * Ncols] =
                make_float2(acc[mt][nt][2], acc[mt][nt][3]);
        }
    }
}

// ---------------------------------------------------------------------------
// Tensor-core flash attention. QK^T: 2-term (q 2-term fp16 x k single fp16).
// PV: single fp16 (2 mmas/chunk). y single fp16.
// Double-buffered 16KB K/V stages (Kh | Vh), causal skip, longest-first.
// ---------------------------------------------------------------------------
#define FQ_B   16384
#define FARR_B 8192
#define FSTAGE_B (2 * FARR_B)                  // Kh,Vh = 16384
#define FLASH_SMEM (2 * FQ_B + 2 * FSTAGE_B)   // 65536

__global__ __launch_bounds__(256, 2) void flash_tc(void)
{
    extern __shared__ uint32_t fw4[];
    const uint32_t sbase = sm2u32(fw4);

    const int tid  = threadIdx.x;
    const int lane = tid & 31;
    const int g    = lane >> 2;
    const int t4   = lane & 3;
    const int m_   = lane >> 3;
    const int j_   = lane & 7;
    const int w    = tid >> 5;
    const int qt   = (int)gridDim.x - 1 - (int)blockIdx.x;  // longest-first
    const int bh   = blockIdx.y;
    const int q0   = qt * 128;
    const int b    = bh >> 4, h = bh & 15;

    const char* qb_src = (const char*)(g_qh  + ((size_t)bh * SS + q0) * DD);
    const char* qs_src = (const char*)(g_qs2 + ((size_t)bh * SS + q0) * DD);
    const char* kb_base = (const char*)(g_kh  + (size_t)bh * SS * DD);
    const char* vh_base = (const char*)(g_vh  + (size_t)bh * DD * SS);

    const int qrow_l = 16 * w + ((m_ & 1) << 3) + j_;
    const int qsw    = qrow_l & 7;
    int krow[4], ksw[4];
#pragma unroll
    for (int p = 0; p < 4; p++) {
        krow[p] = p * 16 + ((m_ >> 1) << 3) + j_;
        ksw[p]  = krow[p] & 7;
    }

    // ---- prologue loads: Q (2 arrays) + KV stage 0 (2 arrays) ----
#pragma unroll
    for (int i = 0; i < 8; i++) {
        const int arr = i >> 2;
        int local = ((i & 3) << 8) + tid;
        int row = local >> 3, c = local & 7;
        uint32_t dst = sbase + arr * FQ_B + row * 128 + ((c ^ (row & 7)) << 4);
        const char* src = (arr ? qs_src : qb_src) + (size_t)row * 128 + c * 16;
        CP16(dst, src);
    }
#pragma unroll
    for (int i = 0; i < 4; i++) {
        const int arr = i >> 1;                 // 0:Kh 1:Vh
        int local = ((i & 1) << 8) + tid;
        int row = local >> 3, c = local & 7;
        uint32_t dst = sbase + 2 * FQ_B + arr * FARR_B + row * 128 +
                       ((c ^ (row & 7)) << 4);
        const char* src;
        if (arr == 0) src = kb_base + (size_t)row * 128 + c * 16;
        else          src = vh_base + (size_t)row * (SS * 2) + c * 16;
        CP16(dst, src);
    }
    CP_COMMIT();

    float s4[8][4], y[8][4];
#pragma unroll
    for (int j = 0; j < 8; j++)
#pragma unroll
        for (int e = 0; e < 4; e++) y[j][e] = 0.0f;
    float m0 = -1e30f, m1 = -1e30f, l0 = 0.0f, l1 = 0.0f;

    const int qrow0 = q0 + 16 * w + g;
    const int qlim  = q0 + 16 * w + 15;
    const int jmax  = 2 * qt + 2;

    for (int jt = 0; jt < jmax; jt++) {
        const int s  = jt & 1;
        const int k0 = jt * 64;

        if (jt + 1 < jmax) {
            const int kn = (jt + 1) * 64;
            const uint32_t stb = sbase + 2 * FQ_B + (s ^ 1) * FSTAGE_B;
#pragma unroll
            for (int i = 0; i < 4; i++) {
                const int arr = i >> 1;
                int local = ((i & 1) << 8) + tid;
                int row = local >> 3, c = local & 7;
                uint32_t dst = stb + arr * FARR_B + row * 128 + ((c ^ (row & 7)) << 4);
                const char* src;
                if (arr == 0) src = kb_base + ((size_t)(kn + row)) * 128 + c * 16;
                else          src = vh_base + (size_t)row * (SS * 2) + kn * 2 + c * 16;
                CP16(dst, src);
            }
            CP_COMMIT();
            asm volatile("cp.async.wait_group 1;");
        } else {
            asm volatile("cp.async.wait_group 0;");
        }
        __syncthreads();

        const bool active = (k0 <= qlim);
        if (active) {
            const uint32_t KbO = sbase + 2 * FQ_B + s * FSTAGE_B;
            const uint32_t VhO = KbO + FARR_B;

            // ---- S = Q K^T (q 2-term x k single: 2 mmas per 16-key pair) ----
#pragma unroll
            for (int j = 0; j < 8; j++)
#pragma unroll
                for (int e = 0; e < 4; e++) s4[j][e] = 0.0f;

#pragma unroll
            for (int ks = 0; ks < 4; ks++) {
                const int cA = ks * 2 + (m_ >> 1);
                const int cB = ks * 2 + (m_ & 1);
                uint32_t qoff = qrow_l * 128 + ((cA ^ qsw) << 4);
                uint32_t ab[4], asf[4];
                ldm4(sbase + qoff, ab);
                ldm4(sbase + FQ_B + qoff, asf);
#pragma unroll
                for (int p = 0; p < 4; p++) {
                    if (k0 + p * 16 <= qlim) {
                        uint32_t off = krow[p] * 128 + ((cB ^ ksw[p]) << 4);
                        uint32_t rb[4];
                        ldm4(KbO + off, rb);
                        mma_f16(s4[2 * p],     ab,  rb[0], rb[1]);
                        mma_f16(s4[2 * p + 1], ab,  rb[2], rb[3]);
                        mma_f16(s4[2 * p],     asf, rb[0], rb[1]);
                        mma_f16(s4[2 * p + 1], asf, rb[2], rb[3]);
                    }
                }
            }

            // ---- scale + causal mask ----
#pragma unroll
            for (int j = 0; j < 8; j++)
#pragma unroll
                for (int e = 0; e < 4; e++) s4[j][e] *= 0.125f;
            if (k0 + 63 > q0 + 16 * w) {
#pragma unroll
                for (int nt = 0; nt < 8; nt++) {
                    int kg = k0 + nt * 8 + 2 * t4;
#pragma unroll
                    for (int e = 0; e < 4; e++) {
                        int kk = kg + (e & 1);
                        int qq = qrow0 + ((e >> 1) << 3);
                        if (kk > qq) s4[nt][e] = -1e30f;
                    }
                }
            }

            // ---- online softmax ----
            float mx0 = -1e30f, mx1 = -1e30f;
#pragma unroll
            for (int j = 0; j < 8; j++) {
                mx0 = fmaxf(mx0, fmaxf(s4[j][0], s4[j][1]));
                mx1 = fmaxf(mx1, fmaxf(s4[j][2], s4[j][3]));
            }
            mx0 = fmaxf(mx0, __shfl_xor_sync(0xffffffffu, mx0, 1));
            mx0 = fmaxf(mx0, __shfl_xor_sync(0xffffffffu, mx0, 2));
            mx1 = fmaxf(mx1, __shfl_xor_sync(0xffffffffu, mx1, 1));
            mx1 = fmaxf(mx1, __shfl_xor_sync(0xffffffffu, mx1, 2));
            float mn0 = fmaxf(m0, mx0), mn1 = fmaxf(m1, mx1);
            float c0 = __expf(m0 - mn0), c1 = __expf(m1 - mn1);
            m0 = mn0; m1 = mn1;
            float sum0 = 0.0f, sum1 = 0.0f;
#pragma unroll
            for (int j = 0; j < 8; j++) {
                s4[j][0] = __expf(s4[j][0] - mn0); sum0 += s4[j][0];
                s4[j][1] = __expf(s4[j][1] - mn0); sum0 += s4[j][1];
                s4[j][2] = __expf(s4[j][2] - mn1); sum1 += s4[j][2];
                s4[j][3] = __expf(s4[j][3] - mn1); sum1 += s4[j][3];
            }
            sum0 += __shfl_xor_sync(0xffffffffu, sum0, 1);
            sum0 += __shfl_xor_sync(0xffffffffu, sum0, 2);
            sum1 += __shfl_xor_sync(0xffffffffu, sum1, 1);
            sum1 += __shfl_xor_sync(0xffffffffu, sum1, 2);
            l0 = l0 * c0 + sum0;
            l1 = l1 * c1 + sum1;
#pragma unroll
            for (int j = 0; j < 8; j++) {
                y[j][0] *= c0; y[j][1] *= c0;
                y[j][2] *= c1; y[j][3] *= c1;
            }

            // ---- Y += P V : P single fp16, V single fp16 ----
#pragma unroll
            for (int kk = 0; kk < 4; kk++) {
                if (k0 + kk * 16 <= qlim) {
                    uint32_t pab[4] = {
                        packh(s4[2 * kk][0],     s4[2 * kk][1]),
                        packh(s4[2 * kk][2],     s4[2 * kk][3]),
                        packh(s4[2 * kk + 1][0], s4[2 * kk + 1][1]),
                        packh(s4[2 * kk + 1][2], s4[2 * kk + 1][3]) };
                    const int cV = kk * 2 + (m_ & 1);
#pragma unroll
                    for (int p = 0; p < 4; p++) {
                        uint32_t off = krow[p] * 128 + ((cV ^ ksw[p]) << 4);
                        uint32_t rv[4];
                        ldm4(VhO + off, rv);
                        mma_f16(y[2 * p],     pab, rv[0], rv[1]);
                        mma_f16(y[2 * p + 1], pab, rv[2], rv[3]);
                    }
                }
            }
        }
        __syncthreads();
    }

    // ---- normalize + write single-fp16 y ----
    float inv0 = 1.0f / l0, inv1 = 1.0f / l1;
    const size_t row0 = (size_t)b * SS + q0 + 16 * w + g;
    const size_t row1 = row0 + 8;
#pragma unroll
    for (int nd = 0; nd < 8; nd++) {
        int col = h * 64 + nd * 8 + 2 * t4;
        *(uint32_t*)&g_yh[row0 * EE + col] = packh(y[nd][0] * inv0, y[nd][1] * inv0);
        *(uint32_t*)&g_yh[row1 * EE + col] = packh(y[nd][2] * inv1, y[nd][3] * inv1);
    }
}

// ---------------------------------------------------------------------------
extern "C" void kernel_launch(void* const* d_in, const int* in_sizes, int n_in,
                              void* d_out, int out_size)
{
    const float* x      = (const float*)d_in[0];
    const float* w_attn = (const float*)d_in[1];
    const float* w_proj = (const float*)d_in[2];
    float* out = (float*)d_out;

    __half *xh, *wah, *wph, *yh;
    cudaGetSymbolAddress((void**)&xh,  g_xh);
    cudaGetSymbolAddress((void**)&wah, g_wah);
    cudaGetSymbolAddress((void**)&wph, g_wph);
    cudaGetSymbolAddress((void**)&yh,  g_yh);

    cudaFuncSetAttribute(h_gemm_qkv, cudaFuncAttributeMaxDynamicSharedMemorySize, GEMM_DSMEM);
    cudaFuncSetAttribute(h_gemm,     cudaFuncAttributeMaxDynamicSharedMemorySize, HG_DSMEM);
    cudaFuncSetAttribute(flash_tc,   cudaFuncAttributeMaxDynamicSharedMemorySize, FLASH_SMEM);

    // 0. convert x (single fp16); transpose weights (single fp16)
    {
        int n4 = M_TOT * EE / 4;
        convert_h_kernel<<<(n4 + 255) / 256, 256>>>(x, xh, n4);
        dim3 tb(32, 8);
        transpose_h_kernel<<<dim3(3 * EE / 32, EE / 32), tb>>>(w_attn, wah, EE, 3 * EE);
        transpose_h_kernel<<<dim3(EE / 32, EE / 32), tb>>>(w_proj, wph, EE, EE);
    }

    // 1. QKV GEMM (1-mma fp16) -> q 2-term + k single + v single
    {
        dim3 grid(3 * EE / 128, M_TOT / 128);   // (24, 64)
        h_gemm_qkv<<<grid, 256, GEMM_DSMEM>>>(xh, wah);
    }

    // 2. flash attention -> single fp16 y
    {
        dim3 grid(SS / 128, BB * HH);           // (16, 64)
        flash_tc<<<grid, 256, FLASH_SMEM>>>();
    }

    // 3. proj GEMM (single fp16) -> out (fp32)
    {
        dim3 grid(EE / 128, M_TOT / 128);       // (8, 64)
        h_gemm<<<grid, 256, HG_DSMEM>>>(yh, wph, out, EE);
    }
}

// round 17
// speedup vs baseline: 2.2021x; 1.0634x over previous
#include <cuda_runtime.h>
#include <cuda_bf16.h>
#include <cuda_fp16.h>
#include <cstdint>

#define BB 4
#define SS 2048
#define EE 1024
#define HH 16
#define DD 64
#define M_TOT (BB * SS)     // 8192
#define KDIM EE             // GEMM K = 1024

// operands (fp16)
__device__ __half g_xh[M_TOT * EE];                               // x single fp16 [M][K]
__device__ __half g_wah[3 * EE * EE];                             // w_attn single fp16 [N][K]
__device__ __half g_wph[EE * EE];                                 // w_proj single fp16 [N][K]
__device__ __half g_qh[BB * HH * SS * DD], g_qs2[BB * HH * SS * DD]; // q 2-term fp16 [b,h,s,d]
__device__ __half g_kh[BB * HH * SS * DD];                        // k single fp16 [b,h,s,d]
__device__ __half g_vh[BB * HH * DD * SS];                        // v single fp16 [b,h,d,s]
__device__ __half g_yh[M_TOT * EE];                               // y single fp16 [M][E]

// ---------------------------------------------------------------------------
// Helpers
// ---------------------------------------------------------------------------
__device__ __forceinline__ uint32_t sm2u32(const void* p) {
    uint32_t a;
    asm("{ .reg .u64 t; cvta.to.shared.u64 t, %1; cvt.u32.u64 %0, t; }"
        : "=r"(a) : "l"(p));
    return a;
}

__device__ __forceinline__ uint32_t packh(float lo, float hi) {
    uint32_t r;
    asm("cvt.rn.f16x2.f32 %0, %1, %2;" : "=r"(r) : "f"(hi), "f"(lo));
    return r;
}

__device__ __forceinline__ void mma_f16(float* c, const uint32_t* a,
                                        uint32_t b0, uint32_t b1) {
    asm volatile(
        "mma.sync.aligned.m16n8k16.row.col.f32.f16.f16.f32 "
        "{%0,%1,%2,%3}, {%4,%5,%6,%7}, {%8,%9}, {%0,%1,%2,%3};\n"
        : "+f"(c[0]), "+f"(c[1]), "+f"(c[2]), "+f"(c[3])
        : "r"(a[0]), "r"(a[1]), "r"(a[2]), "r"(a[3]), "r"(b0), "r"(b1));
}

__device__ __forceinline__ void ldm4(uint32_t addr, uint32_t* r) {
    asm volatile("ldmatrix.sync.aligned.m8n8.x4.shared.b16 {%0,%1,%2,%3}, [%4];"
                 : "=r"(r[0]), "=r"(r[1]), "=r"(r[2]), "=r"(r[3]) : "r"(addr));
}

#define CP16(dst, src) \
    asm volatile("cp.async.cg.shared.global [%0], [%1], 16;" :: "r"(dst), "l"(src))
#define CP_COMMIT() asm volatile("cp.async.commit_group;")

// ---------------------------------------------------------------------------
// Prep kernels
// ---------------------------------------------------------------------------
__global__ void convert_h_kernel(const float* __restrict__ in,
                                 __half* __restrict__ oh, int n4)
{
    int i = blockIdx.x * blockDim.x + threadIdx.x;
    if (i >= n4) return;
    float4 v = ((const float4*)in)[i];
    uint2 p;
    ((uint32_t*)&p)[0] = packh(v.x, v.y);
    ((uint32_t*)&p)[1] = packh(v.z, v.w);
    ((uint2*)oh)[i] = p;
}

// w[K,N] fp32 -> oh [N,K] single fp16
__global__ void transpose_h_kernel(const float* __restrict__ w,
                                   __half* __restrict__ oh, int K, int N)
{
    __shared__ float t[32][33];
    int n0 = blockIdx.x * 32, k0 = blockIdx.y * 32;
    int tx = threadIdx.x, ty = threadIdx.y;
#pragma unroll
    for (int i = 0; i < 4; i++)
        t[ty + i * 8][tx] = w[(size_t)(k0 + ty + i * 8) * N + n0 + tx];
    __syncthreads();
#pragma unroll
    for (int i = 0; i < 4; i++) {
        int n = ty + i * 8;
        oh[(size_t)(n0 + n) * K + k0 + tx] = __float2half_rn(t[tx][n]);
    }
}

// ---------------------------------------------------------------------------
// fp16 1-mma GEMM core, KT=64 (128B rows, SW128 swizzle), 3-stage cp.async,
// block 128x128, warp tile 64x32, occ 2. Template epilogue: 0 = QKV scatter,
// 1 = plain fp32 C.
// ---------------------------------------------------------------------------
#define GKT 64
#define NKT (KDIM / GKT)           // 16
#define GARR_B 16384               // 128 rows * 128 B
#define GSTAGE_B (2 * GARR_B)      // 32768
#define GEMM_DSMEM (3 * GSTAGE_B)  // 98304

template <int MODE>
__global__ __launch_bounds__(256, 2) void h_gemm(
    const __half* __restrict__ Ah, const __half* __restrict__ Btb,
    float* __restrict__ C, int Ncols)
{
    extern __shared__ uint32_t sw4[];
    const uint32_t sbase = sm2u32(sw4);

    const int tid  = threadIdx.x;
    const int lane = tid & 31;
    const int g    = lane >> 2;
    const int t4   = lane & 3;
    const int m_   = lane >> 3;
    const int j_   = lane & 7;
    const int warp = tid >> 5;
    const int wm   = warp & 1;
    const int wn   = warp >> 1;
    const int m0   = blockIdx.y * 128;
    const int n0   = blockIdx.x * 128;

    const char* srcs[2] = {
        (const char*)(Ah  + (size_t)m0 * KDIM),
        (const char*)(Btb + (size_t)n0 * KDIM) };

    int arow[4], asw[4];
#pragma unroll
    for (int mt = 0; mt < 4; mt++) {
        arow[mt] = wm * 64 + mt * 16 + ((m_ & 1) << 3) + j_;
        asw[mt]  = arow[mt] & 7;
    }
    int brow[2], bsw[2];
#pragma unroll
    for (int p = 0; p < 2; p++) {
        brow[p] = wn * 32 + p * 16 + ((m_ >> 1) << 3) + j_;
        bsw[p]  = brow[p] & 7;
    }

    float acc[4][4][4];
#pragma unroll
    for (int i = 0; i < 4; i++)
#pragma unroll
        for (int j = 0; j < 4; j++)
#pragma unroll
            for (int e = 0; e < 4; e++) acc[i][j][e] = 0.0f;

    // stage loader: 2048 16B chunks (2 arrays x 128 rows x 8 chunks)
    auto load_stage = [&](int s, int kt) {
        const uint32_t stb = sbase + s * GSTAGE_B;
#pragma unroll
        for (int i = 0; i < 8; i++) {
            const int arr = i >> 2;
            int local = ((i & 3) << 8) + tid;       // 0..1023
            int row = local >> 3;
            int c   = local & 7;
            uint32_t dst = stb + arr * GARR_B + row * 128 + ((c ^ (row & 7)) << 4);
            const char* src = srcs[arr] + (size_t)row * (KDIM * 2) + kt * 128 + c * 16;
            CP16(dst, src);
        }
        CP_COMMIT();
    };

    load_stage(0, 0);
    load_stage(1, 1);

    for (int kt = 0; kt < NKT; kt++) {
        const int s = kt % 3;
        if (kt + 1 < NKT) {
            asm volatile("cp.async.wait_group 1;");
        } else {
            asm volatile("cp.async.wait_group 0;");
        }
        __syncthreads();
        if (kt + 2 < NKT) load_stage((kt + 2) % 3, kt + 2);

        const uint32_t AO = sbase + s * GSTAGE_B;
        const uint32_t BO = AO + GARR_B;

#pragma unroll
        for (int ks = 0; ks < 4; ks++) {
            const int cA = ks * 2 + (m_ >> 1);
            const int cB = ks * 2 + (m_ & 1);

            uint32_t bb[4][2];
#pragma unroll
            for (int p = 0; p < 2; p++) {
                uint32_t off = brow[p] * 128 + ((cB ^ bsw[p]) << 4);
                uint32_t r[4];
                ldm4(BO + off, r);
                bb[2 * p][0] = r[0];     bb[2 * p][1] = r[1];
                bb[2 * p + 1][0] = r[2]; bb[2 * p + 1][1] = r[3];
            }
#pragma unroll
            for (int mt = 0; mt < 4; mt++) {
                uint32_t off = arow[mt] * 128 + ((cA ^ asw[mt]) << 4);
                uint32_t ab[4];
                ldm4(AO + off, ab);
#pragma unroll
                for (int nt = 0; nt < 4; nt++)
                    mma_f16(acc[mt][nt], ab, bb[nt][0], bb[nt][1]);
            }
        }
    }

    // ---- epilogue ----
#pragma unroll
    for (int mt = 0; mt < 4; mt++) {
#pragma unroll
        for (int nt = 0; nt < 4; nt++) {
            const int r  = m0 + wm * 64 + mt * 16 + g;
            const int cc = n0 + wn * 32 + nt * 8 + 2 * t4;
            float v0 = acc[mt][nt][0], v1 = acc[mt][nt][1];
            float v2 = acc[mt][nt][2], v3 = acc[mt][nt][3];
            if (MODE == 1) {
                size_t i0 = (size_t)r * Ncols + cc;
                *(float2*)&C[i0] = make_float2(v0, v1);
                *(float2*)&C[i0 + (size_t)8 * Ncols] = make_float2(v2, v3);
            } else {
                const int sec = cc >> 10;
                const int c10 = cc & 1023;
                const int h   = c10 >> 6;
                const int d0  = c10 & 63;
                const int b   = r >> 11;
                const int sl  = r & 2047;
                if (sec == 0) {
                    float b0 = __half2float(__float2half_rn(v0));
                    float b1 = __half2float(__float2half_rn(v1));
                    float b2 = __half2float(__float2half_rn(v2));
                    float b3 = __half2float(__float2half_rn(v3));
                    size_t i0 = (((size_t)(b * HH + h)) * SS + sl) * DD + d0;
                    *(uint32_t*)&g_qh[i0]  = packh(b0, b1);
                    *(uint32_t*)&g_qs2[i0] = packh(v0 - b0, v1 - b1);
                    *(uint32_t*)&g_qh[i0 + 8 * DD]  = packh(b2, b3);
                    *(uint32_t*)&g_qs2[i0 + 8 * DD] = packh(v2 - b2, v3 - b3);
                } else if (sec == 1) {
                    size_t i0 = (((size_t)(b * HH + h)) * SS + sl) * DD + d0;
                    *(uint32_t*)&g_kh[i0]          = packh(v0, v1);
                    *(uint32_t*)&g_kh[i0 + 8 * DD] = packh(v2, v3);
                } else {
                    size_t base = ((size_t)(b * HH + h)) * DD * SS;
                    size_t iA = base + (size_t)d0 * SS + sl;
                    size_t iB = base + (size_t)(d0 + 1) * SS + sl;
                    g_vh[iA]     = __float2half_rn(v0);
                    g_vh[iB]     = __float2half_rn(v1);
                    g_vh[iA + 8] = __float2half_rn(v2);
                    g_vh[iB + 8] = __float2half_rn(v3);
                }
            }
        }
    }
}

// ---------------------------------------------------------------------------
// Tensor-core flash attention (unchanged from R16). QK^T: q 2-term x k single
// (2 mmas/pair). PV: single fp16 (2 mmas/chunk). y single fp16.
// ---------------------------------------------------------------------------
#define FQ_B   16384
#define FARR_B 8192
#define FSTAGE_B (2 * FARR_B)                  // Kh,Vh = 16384
#define FLASH_SMEM (2 * FQ_B + 2 * FSTAGE_B)   // 65536

__global__ __launch_bounds__(256, 2) void flash_tc(void)
{
    extern __shared__ uint32_t fw4[];
    const uint32_t sbase = sm2u32(fw4);

    const int tid  = threadIdx.x;
    const int lane = tid & 31;
    const int g    = lane >> 2;
    const int t4   = lane & 3;
    const int m_   = lane >> 3;
    const int j_   = lane & 7;
    const int w    = tid >> 5;
    const int qt   = (int)gridDim.x - 1 - (int)blockIdx.x;  // longest-first
    const int bh   = blockIdx.y;
    const int q0   = qt * 128;
    const int b    = bh >> 4, h = bh & 15;

    const char* qb_src = (const char*)(g_qh  + ((size_t)bh * SS + q0) * DD);
    const char* qs_src = (const char*)(g_qs2 + ((size_t)bh * SS + q0) * DD);
    const char* kb_base = (const char*)(g_kh  + (size_t)bh * SS * DD);
    const char* vh_base = (const char*)(g_vh  + (size_t)bh * DD * SS);

    const int qrow_l = 16 * w + ((m_ & 1) << 3) + j_;
    const int qsw    = qrow_l & 7;
    int krow[4], ksw[4];
#pragma unroll
    for (int p = 0; p < 4; p++) {
        krow[p] = p * 16 + ((m_ >> 1) << 3) + j_;
        ksw[p]  = krow[p] & 7;
    }

    // ---- prologue loads: Q (2 arrays) + KV stage 0 (2 arrays) ----
#pragma unroll
    for (int i = 0; i < 8; i++) {
        const int arr = i >> 2;
        int local = ((i & 3) << 8) + tid;
        int row = local >> 3, c = local & 7;
        uint32_t dst = sbase + arr * FQ_B + row * 128 + ((c ^ (row & 7)) << 4);
        const char* src = (arr ? qs_src : qb_src) + (size_t)row * 128 + c * 16;
        CP16(dst, src);
    }
#pragma unroll
    for (int i = 0; i < 4; i++) {
        const int arr = i >> 1;                 // 0:Kh 1:Vh
        int local = ((i & 1) << 8) + tid;
        int row = local >> 3, c = local & 7;
        uint32_t dst = sbase + 2 * FQ_B + arr * FARR_B + row * 128 +
                       ((c ^ (row & 7)) << 4);
        const char* src;
        if (arr == 0) src = kb_base + (size_t)row * 128 + c * 16;
        else          src = vh_base + (size_t)row * (SS * 2) + c * 16;
        CP16(dst, src);
    }
    CP_COMMIT();

    float s4[8][4], y[8][4];
#pragma unroll
    for (int j = 0; j < 8; j++)
#pragma unroll
        for (int e = 0; e < 4; e++) y[j][e] = 0.0f;
    float m0 = -1e30f, m1 = -1e30f, l0 = 0.0f, l1 = 0.0f;

    const int qrow0 = q0 + 16 * w + g;
    const int qlim  = q0 + 16 * w + 15;
    const int jmax  = 2 * qt + 2;

    for (int jt = 0; jt < jmax; jt++) {
        const int s  = jt & 1;
        const int k0 = jt * 64;

        if (jt + 1 < jmax) {
            const int kn = (jt + 1) * 64;
            const uint32_t stb = sbase + 2 * FQ_B + (s ^ 1) * FSTAGE_B;
#pragma unroll
            for (int i = 0; i < 4; i++) {
                const int arr = i >> 1;
                int local = ((i & 1) << 8) + tid;
                int row = local >> 3, c = local & 7;
                uint32_t dst = stb + arr * FARR_B + row * 128 + ((c ^ (row & 7)) << 4);
                const char* src;
                if (arr == 0) src = kb_base + ((size_t)(kn + row)) * 128 + c * 16;
                else          src = vh_base + (size_t)row * (SS * 2) + kn * 2 + c * 16;
                CP16(dst, src);
            }
            CP_COMMIT();
            asm volatile("cp.async.wait_group 1;");
        } else {
            asm volatile("cp.async.wait_group 0;");
        }
        __syncthreads();

        const bool active = (k0 <= qlim);
        if (active) {
            const uint32_t KbO = sbase + 2 * FQ_B + s * FSTAGE_B;
            const uint32_t VhO = KbO + FARR_B;

            // ---- S = Q K^T ----
#pragma unroll
            for (int j = 0; j < 8; j++)
#pragma unroll
                for (int e = 0; e < 4; e++) s4[j][e] = 0.0f;

#pragma unroll
            for (int ks = 0; ks < 4; ks++) {
                const int cA = ks * 2 + (m_ >> 1);
                const int cB = ks * 2 + (m_ & 1);
                uint32_t qoff = qrow_l * 128 + ((cA ^ qsw) << 4);
                uint32_t ab[4], asf[4];
                ldm4(sbase + qoff, ab);
                ldm4(sbase + FQ_B + qoff, asf);
#pragma unroll
                for (int p = 0; p < 4; p++) {
                    if (k0 + p * 16 <= qlim) {
                        uint32_t off = krow[p] * 128 + ((cB ^ ksw[p]) << 4);
                        uint32_t rb[4];
                        ldm4(KbO + off, rb);
                        mma_f16(s4[2 * p],     ab,  rb[0], rb[1]);
                        mma_f16(s4[2 * p + 1], ab,  rb[2], rb[3]);
                        mma_f16(s4[2 * p],     asf, rb[0], rb[1]);
                        mma_f16(s4[2 * p + 1], asf, rb[2], rb[3]);
                    }
                }
            }

            // ---- scale + causal mask ----
#pragma unroll
            for (int j = 0; j < 8; j++)
#pragma unroll
                for (int e = 0; e < 4; e++) s4[j][e] *= 0.125f;
            if (k0 + 63 > q0 + 16 * w) {
#pragma unroll
                for (int nt = 0; nt < 8; nt++) {
                    int kg = k0 + nt * 8 + 2 * t4;
#pragma unroll
                    for (int e = 0; e < 4; e++) {
                        int kk = kg + (e & 1);
                        int qq = qrow0 + ((e >> 1) << 3);
                        if (kk > qq) s4[nt][e] = -1e30f;
                    }
                }
            }

            // ---- online softmax ----
            float mx0 = -1e30f, mx1 = -1e30f;
#pragma unroll
            for (int j = 0; j < 8; j++) {
                mx0 = fmaxf(mx0, fmaxf(s4[j][0], s4[j][1]));
                mx1 = fmaxf(mx1, fmaxf(s4[j][2], s4[j][3]));
            }
            mx0 = fmaxf(mx0, __shfl_xor_sync(0xffffffffu, mx0, 1));
            mx0 = fmaxf(mx0, __shfl_xor_sync(0xffffffffu, mx0, 2));
            mx1 = fmaxf(mx1, __shfl_xor_sync(0xffffffffu, mx1, 1));
            mx1 = fmaxf(mx1, __shfl_xor_sync(0xffffffffu, mx1, 2));
            float mn0 = fmaxf(m0, mx0), mn1 = fmaxf(m1, mx1);
            float c0 = __expf(m0 - mn0), c1 = __expf(m1 - mn1);
            m0 = mn0; m1 = mn1;
            float sum0 = 0.0f, sum1 = 0.0f;
#pragma unroll
            for (int j = 0; j < 8; j++) {
                s4[j][0] = __expf(s4[j][0] - mn0); sum0 += s4[j][0];
                s4[j][1] = __expf(s4[j][1] - mn0); sum0 += s4[j][1];
                s4[j][2] = __expf(s4[j][2] - mn1); sum1 += s4[j][2];
                s4[j][3] = __expf(s4[j][3] - mn1); sum1 += s4[j][3];
            }
            sum0 += __shfl_xor_sync(0xffffffffu, sum0, 1);
            sum0 += __shfl_xor_sync(0xffffffffu, sum0, 2);
            sum1 += __shfl_xor_sync(0xffffffffu, sum1, 1);
            sum1 += __shfl_xor_sync(0xffffffffu, sum1, 2);
            l0 = l0 * c0 + sum0;
            l1 = l1 * c1 + sum1;
#pragma unroll
            for (int j = 0; j < 8; j++) {
                y[j][0] *= c0; y[j][1] *= c0;
                y[j][2] *= c1; y[j][3] *= c1;
            }

            // ---- Y += P V ----
#pragma unroll
            for (int kk = 0; kk < 4; kk++) {
                if (k0 + kk * 16 <= qlim) {
                    uint32_t pab[4] = {
                        packh(s4[2 * kk][0],     s4[2 * kk][1]),
                        packh(s4[2 * kk][2],     s4[2 * kk][3]),
                        packh(s4[2 * kk + 1][0], s4[2 * kk + 1][1]),
                        packh(s4[2 * kk + 1][2], s4[2 * kk + 1][3]) };
                    const int cV = kk * 2 + (m_ & 1);
#pragma unroll
                    for (int p = 0; p < 4; p++) {
                        uint32_t off = krow[p] * 128 + ((cV ^ ksw[p]) << 4);
                        uint32_t rv[4];
                        ldm4(VhO + off, rv);
                        mma_f16(y[2 * p],     pab, rv[0], rv[1]);
                        mma_f16(y[2 * p + 1], pab, rv[2], rv[3]);
                    }
                }
            }
        }
        __syncthreads();
    }

    // ---- normalize + write single-fp16 y ----
    float inv0 = 1.0f / l0, inv1 = 1.0f / l1;
    const size_t row0 = (size_t)b * SS + q0 + 16 * w + g;
    const size_t row1 = row0 + 8;
#pragma unroll
    for (int nd = 0; nd < 8; nd++) {
        int col = h * 64 + nd * 8 + 2 * t4;
        *(uint32_t*)&g_yh[row0 * EE + col] = packh(y[nd][0] * inv0, y[nd][1] * inv0);
        *(uint32_t*)&g_yh[row1 * EE + col] = packh(y[nd][2] * inv1, y[nd][3] * inv1);
    }
}

// ---------------------------------------------------------------------------
extern "C" void kernel_launch(void* const* d_in, const int* in_sizes, int n_in,
                              void* d_out, int out_size)
{
    const float* x      = (const float*)d_in[0];
    const float* w_attn = (const float*)d_in[1];
    const float* w_proj = (const float*)d_in[2];
    float* out = (float*)d_out;

    __half *xh, *wah, *wph, *yh;
    cudaGetSymbolAddress((void**)&xh,  g_xh);
    cudaGetSymbolAddress((void**)&wah, g_wah);
    cudaGetSymbolAddress((void**)&wph, g_wph);
    cudaGetSymbolAddress((void**)&yh,  g_yh);

    cudaFuncSetAttribute(h_gemm<0>, cudaFuncAttributeMaxDynamicSharedMemorySize, GEMM_DSMEM);
    cudaFuncSetAttribute(h_gemm<1>, cudaFuncAttributeMaxDynamicSharedMemorySize, GEMM_DSMEM);
    cudaFuncSetAttribute(flash_tc,  cudaFuncAttributeMaxDynamicSharedMemorySize, FLASH_SMEM);

    // 0. convert x; transpose weights (single fp16)
    {
        int n4 = M_TOT * EE / 4;
        convert_h_kernel<<<(n4 + 255) / 256, 256>>>(x, xh, n4);
        dim3 tb(32, 8);
        transpose_h_kernel<<<dim3(3 * EE / 32, EE / 32), tb>>>(w_attn, wah, EE, 3 * EE);
        transpose_h_kernel<<<dim3(EE / 32, EE / 32), tb>>>(w_proj, wph, EE, EE);
    }

    // 1. QKV GEMM (KT=64) -> q 2-term + k single + v single
    {
        dim3 grid(3 * EE / 128, M_TOT / 128);   // (24, 64)
        h_gemm<0><<<grid, 256, GEMM_DSMEM>>>(xh, wah, nullptr, 3 * EE);
    }

    // 2. flash attention -> single fp16 y
    {
        dim3 grid(SS / 128, BB * HH);           // (16, 64)
        flash_tc<<<grid, 256, FLASH_SMEM>>>();
    }

    // 3. proj GEMM (KT=64) -> out (fp32)
    {
        dim3 grid(EE / 128, M_TOT / 128);       // (8, 64)
        h_gemm<1><<<grid, 256, GEMM_DSMEM>>>(yh, wph, out, EE);
    }
}